// round 6
// baseline (speedup 1.0000x reference)
#include <cuda_runtime.h>

#define MBATCH 32
#define ET 4
#define NN 512
#define IN0 64
#define HID 128
#define ROWS (MBATCH*NN)      /* 16384 */
#define MAXNBR 64
#define KP0 336               /* pad(5*64+4, 16)  */
#define KP12 656              /* pad(5*128+4, 16) */
#define EPSV 1e-5f

/* weight-concat row offsets inside g_W */
#define WO0 0
#define WO1 336
#define WO2 992
#define WO3 1648
#define WO4 1776
#define WROWS 1904

/* ---------------- static device scratch (no allocation) ---------------- */
__device__ float          g_inv[MBATCH*NN];
__device__ float          g_ssum[MBATCH*ET*NN];
__device__ unsigned short g_nbr[MBATCH*ET*NN*MAXNBR];
__device__ int            g_cnt[MBATCH*ET*NN];              // clamped
__device__ int            g_cntfull[MBATCH*ET*NN];          // exact
__device__ float          g_A[ROWS*KP12];
__device__ float          g_W[WROWS*HID];
__device__ float          g_pre[ROWS*HID];
__device__ float          g_h[ROWS*HID];
__device__ float          g_scale[NN];
__device__ float          g_shift[NN];

__device__ __forceinline__ float f2tf(float x) {
    unsigned r;
    asm("cvt.rna.tf32.f32 %0, %1;" : "=r"(r) : "f"(x));
    return __uint_as_float(r);
}

/* ------------- 1) CSR build: one warp per (b,e,n) row, float4 reads ----- */
__global__ void k_csr(const float* __restrict__ adj) {
    int row  = blockIdx.x * 8 + (threadIdx.x >> 5);
    int lane = threadIdx.x & 31;
    int n    = row & (NN - 1);
    const float4* p = (const float4*)(adj + (size_t)row * NN);
    unsigned short* out = g_nbr + (size_t)row * MAXNBR;
    int cnt = 0;
    for (int it = 0; it < NN / 128; it++) {
        float4 v = p[it * 32 + lane];
        int mb = (it * 32 + lane) * 4;
        float vc[4] = {v.x, v.y, v.z, v.w};
#pragma unroll
        for (int c = 0; c < 4; c++) {
            bool pr = (vc[c] != 0.f) && (mb + c != n);
            unsigned msk = __ballot_sync(0xffffffffu, pr);
            if (pr) {
                int pos = cnt + __popc(msk & ((1u << lane) - 1u));
                if (pos < MAXNBR) out[pos] = (unsigned short)(mb + c);
            }
            cnt += __popc(msk);
        }
    }
    if (lane == 0) {
        g_cnt[row]     = cnt < MAXNBR ? cnt : MAXNBR;
        g_cntfull[row] = cnt;
    }
}

/* ------------- 2) inv degree from exact counts (adj symmetric, 0/1) ---- */
__global__ void k_deg() {
    int i = blockIdx.x * 256 + threadIdx.x;   // b*512+m
    int b = i >> 9, m = i & 511;
    int d = 0;
#pragma unroll
    for (int e = 0; e < ET; e++) d += g_cntfull[((b * ET + e) << 9) + m];
    g_inv[i] = d > 0 ? 1.f / (float)d : 0.f;
}

/* ------------- 3) per-row sum of inv over neighbors (layer-invariant) -- */
__global__ void k_ssum() {
    int lidx = blockIdx.x * 256 + threadIdx.x;  // < MB*ET*NN
    int b = lidx >> 11;
    int cnt = g_cnt[lidx];
    const unsigned short* nb = g_nbr + (size_t)lidx * MAXNBR;
    const float* invb = g_inv + b * NN;
    float s = 0.f;
    for (int i = 0; i < cnt; i++) s += invb[nb[i]];
    g_ssum[lidx] = s;
}

/* ------------- 4) ALL weight prep in one kernel, tf32-rounded ---------- */
__global__ void k_wprep_all(
    const float* __restrict__ ws0, const float* __restrict__ we0, const float* __restrict__ be0,
    const float* __restrict__ ws1, const float* __restrict__ we1, const float* __restrict__ be1,
    const float* __restrict__ ws2, const float* __restrict__ we2, const float* __restrict__ be2,
    const float* __restrict__ w1,  const float* __restrict__ w2) {
    int idx = blockIdx.x * 256 + threadIdx.x;
    if (idx >= WROWS * HID) return;
    int k = idx >> 7, o = idx & 127;
    float v = 0.f;
    if (k < WO1) {                       /* layer0: IN=64, KP=336 */
        int kk = k;
        if (kk < 64)       v = ws0[kk * HID + o];
        else if (kk < 320) { int e = (kk - 64) >> 6, j = (kk - 64) & 63;
                             v = we0[j * (HID * ET) + o * ET + e]; }
        else if (kk < 324)   v = be0[o * ET + (kk - 320)];
    } else if (k < WO2) {                /* layer1: IN=128, KP=656 */
        int kk = k - WO1;
        if (kk < 128)      v = ws1[kk * HID + o];
        else if (kk < 640) { int e = (kk - 128) >> 7, j = (kk - 128) & 127;
                             v = we1[j * (HID * ET) + o * ET + e]; }
        else if (kk < 644)   v = be1[o * ET + (kk - 640)];
    } else if (k < WO3) {                /* layer2 */
        int kk = k - WO2;
        if (kk < 128)      v = ws2[kk * HID + o];
        else if (kk < 640) { int e = (kk - 128) >> 7, j = (kk - 128) & 127;
                             v = we2[j * (HID * ET) + o * ET + e]; }
        else if (kk < 644)   v = be2[o * ET + (kk - 640)];
    } else if (k < WO4) {
        v = w1[(k - WO3) * HID + o];
    } else {
        v = w2[(k - WO4) * HID + o];
    }
    g_W[k * HID + o] = f2tf(v);
}

/* ------------- 5) smem-staged aggregation ------------------------------ */
/* block = (eh, cg, b): stages inv[m]*act(h[b,m, cg*32..+32)) for all 512  */
/* nodes in smem (conflict-free: bank==lane), fuses BN+ReLU (IN==128) and */
/* the self-copy into the load pass, then gathers all (n,e) rows.          */
template<int IN, int EPB>
__global__ void __launch_bounds__(256) k_agg_s(const float* __restrict__ srcp, int KP) {
    extern __shared__ float hs[];       // NN*32 floats = 64 KB
    const float* src = srcp ? srcp : (const float*)g_pre;
    int b  = blockIdx.z;
    int cg = blockIdx.y;
    int eh = blockIdx.x;
    int tid = threadIdx.x, lane = tid & 31, warp = tid >> 5;
    int c0 = cg * 32;
    const float* __restrict__ invb = g_inv + b * NN;

    /* load + BN/ReLU + self-copy */
    for (int idx = tid; idx < NN * 32; idx += 256) {
        int m = idx >> 5, c = idx & 31;
        float v = src[(size_t)(b * NN + m) * IN + c0 + c];
        if (IN == HID) v = fmaxf(v * g_scale[m] + g_shift[m], 0.f);
        if (eh == 0) g_A[(size_t)(b * NN + m) * KP + c0 + c] = f2tf(v);
        hs[m * 32 + c] = invb[m] * v;
    }
    /* zero-pad tail cols (12 per row), once per (b) */
    if (cg == 0 && eh == 0) {
        for (int idx = tid; idx < NN * 12; idx += 256) {
            int m = idx / 12, c = idx - m * 12;
            g_A[(size_t)(b * NN + m) * KP + 5 * IN + 4 + c] = 0.f;
        }
    }
    __syncthreads();

    /* gather: rows = (n, e) pairs */
    const int R = NN * EPB;
    for (int rowi = warp; rowi < R; rowi += 8) {
        int e, n;
        if (EPB == 4) { e = rowi & 3; n = rowi >> 2; }
        else          { e = rowi & 1; n = rowi >> 1; }
        int eg = (EPB == 4) ? e : (eh * 2 + e);
        int lidx = ((b * ET + eg) << 9) + n;
        int cnt = g_cnt[lidx];
        const unsigned short* nb = g_nbr + (size_t)lidx * MAXNBR;
        int mreg  = (lane < cnt)      ? (int)nb[lane]      : 0;
        int mreg2 = (lane + 32 < cnt) ? (int)nb[lane + 32] : 0;

        float a0 = 0.f, a1 = 0.f, a2 = 0.f, a3 = 0.f;
        int kmax = cnt < 32 ? cnt : 32;
        int i = 0;
        for (; i + 4 <= kmax; i += 4) {
            int ma = __shfl_sync(0xffffffffu, mreg, i);
            int mb2 = __shfl_sync(0xffffffffu, mreg, i + 1);
            int mc = __shfl_sync(0xffffffffu, mreg, i + 2);
            int md = __shfl_sync(0xffffffffu, mreg, i + 3);
            a0 += hs[ma * 32 + lane];
            a1 += hs[mb2 * 32 + lane];
            a2 += hs[mc * 32 + lane];
            a3 += hs[md * 32 + lane];
        }
        for (; i < kmax; i++) {
            int m = __shfl_sync(0xffffffffu, mreg, i);
            a0 += hs[m * 32 + lane];
        }
        if (cnt > 32) {
            int k2 = cnt - 32;
            i = 0;
            for (; i + 4 <= k2; i += 4) {
                int ma = __shfl_sync(0xffffffffu, mreg2, i);
                int mb2 = __shfl_sync(0xffffffffu, mreg2, i + 1);
                int mc = __shfl_sync(0xffffffffu, mreg2, i + 2);
                int md = __shfl_sync(0xffffffffu, mreg2, i + 3);
                a0 += hs[ma * 32 + lane];
                a1 += hs[mb2 * 32 + lane];
                a2 += hs[mc * 32 + lane];
                a3 += hs[md * 32 + lane];
            }
            for (; i < k2; i++) {
                int m = __shfl_sync(0xffffffffu, mreg2, i);
                a0 += hs[m * 32 + lane];
            }
        }
        float acc = (a0 + a1) + (a2 + a3);
        float* Arow = g_A + (size_t)(b * NN + n) * KP;
        Arow[IN + eg * IN + c0 + lane] = f2tf(acc);
        if (cg == 0 && lane == 0) Arow[5 * IN + eg] = f2tf(g_ssum[lidx]);
    }
}

/* ------------- 6) TF32 GEMM: 128x128 tile, 256 thr, cp.async 2-stage --- */
#define SAW 24
#define SBW 136

__device__ __forceinline__ unsigned smaddr(const void* p) {
    return (unsigned)__cvta_generic_to_shared(p);
}
__device__ __forceinline__ void cpasync16(unsigned s, const void* g) {
    asm volatile("cp.async.cg.shared.global [%0], [%1], 16;\n" :: "r"(s), "l"(g));
}

__global__ void __launch_bounds__(256) k_gemm(int KP, const float* __restrict__ bias,
                                              int srcH, float* __restrict__ Cout,
                                              int wofs) {
    const float* A = srcH ? (const float*)g_h : (const float*)g_A;
    const float* W = (const float*)g_W + (size_t)wofs * HID;
    float* C = Cout ? Cout : (float*)g_pre;

    __shared__ float sA[2][128 * SAW];
    __shared__ float sB[2][16 * SBW];

    int tid = threadIdx.x;
    int lane = tid & 31, warp = tid >> 5;
    int wm = (warp >> 1) * 32, wn = (warp & 1) * 64;
    int grp = lane >> 2, qid = lane & 3;
    int rowbase = blockIdx.x * 128;
    int KB = KP >> 4;

    float acc[2][8][4];
#pragma unroll
    for (int a = 0; a < 2; a++)
#pragma unroll
        for (int bq = 0; bq < 8; bq++)
#pragma unroll
            for (int c = 0; c < 4; c++) acc[a][bq][c] = 0.f;

    auto issue = [&](int kb, int buf) {
        int kof = kb * 16;
#pragma unroll
        for (int i = 0; i < 2; i++) {
            int t = tid + i * 256, rr = t >> 2, q = t & 3;
            cpasync16(smaddr(&sA[buf][rr * SAW + q * 4]),
                      A + (size_t)(rowbase + rr) * KP + kof + q * 4);
        }
#pragma unroll
        for (int i = 0; i < 2; i++) {
            int t = tid + i * 256, kr = t >> 5, c4 = t & 31;
            cpasync16(smaddr(&sB[buf][kr * SBW + c4 * 4]),
                      W + (size_t)(kof + kr) * HID + c4 * 4);
        }
        asm volatile("cp.async.commit_group;\n" ::);
    };

    issue(0, 0);
    for (int kb = 0; kb < KB; kb++) {
        int buf = kb & 1;
        if (kb + 1 < KB) {
            issue(kb + 1, buf ^ 1);
            asm volatile("cp.async.wait_group 1;\n" ::);
        } else {
            asm volatile("cp.async.wait_group 0;\n" ::);
        }
        __syncthreads();

#pragma unroll
        for (int ks = 0; ks < 2; ks++) {
            int k0 = ks * 8;
            unsigned bf[8][2];
#pragma unroll
            for (int ni = 0; ni < 8; ni++) {
                const float* bp = &sB[buf][(k0 + qid) * SBW + wn + ni * 8 + grp];
                bf[ni][0] = __float_as_uint(bp[0]);
                bf[ni][1] = __float_as_uint(bp[4 * SBW]);
            }
#pragma unroll
            for (int mi = 0; mi < 2; mi++) {
                const float* ap = &sA[buf][(wm + mi * 16 + grp) * SAW + k0 + qid];
                unsigned a0 = __float_as_uint(ap[0]);
                unsigned a1 = __float_as_uint(ap[8 * SAW]);
                unsigned a2 = __float_as_uint(ap[4]);
                unsigned a3 = __float_as_uint(ap[8 * SAW + 4]);
#pragma unroll
                for (int ni = 0; ni < 8; ni++) {
                    asm volatile(
                        "mma.sync.aligned.m16n8k8.row.col.f32.tf32.tf32.f32 "
                        "{%0,%1,%2,%3}, {%4,%5,%6,%7}, {%8,%9}, {%0,%1,%2,%3};\n"
                        : "+f"(acc[mi][ni][0]), "+f"(acc[mi][ni][1]),
                          "+f"(acc[mi][ni][2]), "+f"(acc[mi][ni][3])
                        : "r"(a0), "r"(a1), "r"(a2), "r"(a3),
                          "r"(bf[ni][0]), "r"(bf[ni][1]));
                }
            }
        }
        __syncthreads();
    }

#pragma unroll
    for (int mi = 0; mi < 2; mi++) {
        int row = rowbase + wm + mi * 16 + grp;
#pragma unroll
        for (int ni = 0; ni < 8; ni++) {
            int col = wn + ni * 8 + qid * 2;
            float b0 = bias[col], b1 = bias[col + 1];
            C[(size_t)row * HID + col]           = acc[mi][ni][0] + b0;
            C[(size_t)row * HID + col + 1]       = acc[mi][ni][1] + b1;
            C[(size_t)(row + 8) * HID + col]     = acc[mi][ni][2] + b0;
            C[(size_t)(row + 8) * HID + col + 1] = acc[mi][ni][3] + b1;
        }
    }
}

/* ------------- 7) BN stats per node (single pass: sum, sumsq) ---------- */
__global__ void k_bnstats(const float* __restrict__ g, const float* __restrict__ bb) {
    int n = blockIdx.x, o = threadIdx.x;
    const float* pre = (const float*)g_pre;
    __shared__ float rs[128], rq[128];
    float s = 0.f, q = 0.f;
    for (int b = 0; b < MBATCH; b++) {
        float v = pre[(size_t)(b * NN + n) * HID + o];
        s += v;
        q += v * v;
    }
    rs[o] = s; rq[o] = q; __syncthreads();
    for (int st = 64; st > 0; st >>= 1) {
        if (o < st) { rs[o] += rs[o + st]; rq[o] += rq[o + st]; }
        __syncthreads();
    }
    if (o == 0) {
        float mean = rs[0] * (1.f / (MBATCH * HID));
        float var  = rq[0] * (1.f / (MBATCH * HID)) - mean * mean;
        if (var < 0.f) var = 0.f;
        float sc = g[n] * rsqrtf(var + EPSV);
        g_scale[n] = sc;
        g_shift[n] = bb[n] - mean * sc;
    }
}

/* ------------- 8) BN apply + ReLU (float4), tf32-round ----------------- */
__global__ void k_bnapply() {
    int i4 = blockIdx.x * 256 + threadIdx.x;
    float4 v = ((const float4*)g_pre)[i4];
    int r = i4 >> 5;
    int n = r & 511;
    float sc = g_scale[n], sh = g_shift[n];
    v.x = f2tf(fmaxf(v.x * sc + sh, 0.f));
    v.y = f2tf(fmaxf(v.y * sc + sh, 0.f));
    v.z = f2tf(fmaxf(v.z * sc + sh, 0.f));
    v.w = f2tf(fmaxf(v.w * sc + sh, 0.f));
    ((float4*)g_h)[i4] = v;
}

/* ---------------- driver ------------------------------------------------ */
extern "C" void kernel_launch(void* const* d_in, const int* in_sizes, int n_in,
                              void* d_out, int out_size) {
    const float* x   = (const float*)d_in[0];
    const float* adj = (const float*)d_in[1];
    const float* ws[3] = {(const float*)d_in[2],  (const float*)d_in[8],  (const float*)d_in[14]};
    const float* bs[3] = {(const float*)d_in[3],  (const float*)d_in[9],  (const float*)d_in[15]};
    const float* we[3] = {(const float*)d_in[4],  (const float*)d_in[10], (const float*)d_in[16]};
    const float* be[3] = {(const float*)d_in[5],  (const float*)d_in[11], (const float*)d_in[17]};
    const float* bg[3] = {(const float*)d_in[6],  (const float*)d_in[12], (const float*)d_in[18]};
    const float* bb[3] = {(const float*)d_in[7],  (const float*)d_in[13], (const float*)d_in[19]};
    const float* w1  = (const float*)d_in[20];
    const float* b1  = (const float*)d_in[21];
    const float* bfg = (const float*)d_in[22];
    const float* bfb = (const float*)d_in[23];
    const float* w2  = (const float*)d_in[24];
    const float* b2  = (const float*)d_in[25];

    (void)in_sizes; (void)n_in; (void)out_size;

    const int AGG_SMEM = NN * 32 * (int)sizeof(float);   /* 64 KB */
    cudaFuncSetAttribute(k_agg_s<IN0, 2>, cudaFuncAttributeMaxDynamicSharedMemorySize, AGG_SMEM);
    cudaFuncSetAttribute(k_agg_s<HID, 4>, cudaFuncAttributeMaxDynamicSharedMemorySize, AGG_SMEM);

    k_csr<<<(MBATCH * ET * NN) / 8, 256>>>(adj);
    k_deg<<<(MBATCH * NN) / 256, 256>>>();
    k_ssum<<<(MBATCH * ET * NN) / 256, 256>>>();
    k_wprep_all<<<(WROWS * HID + 255) / 256, 256>>>(
        ws[0], we[0], be[0], ws[1], we[1], be[1], ws[2], we[2], be[2], w1, w2);

    /* layer 0 */
    k_agg_s<IN0, 2><<<dim3(2, 2, MBATCH), 256, AGG_SMEM>>>(x, KP0);
    k_gemm<<<ROWS / 128, 256>>>(KP0, bs[0], 0, nullptr, WO0);
    k_bnstats<<<NN, 128>>>(bg[0], bb[0]);

    /* layer 1 (BN fused into agg load) */
    k_agg_s<HID, 4><<<dim3(1, 4, MBATCH), 256, AGG_SMEM>>>((const float*)nullptr, KP12);
    k_gemm<<<ROWS / 128, 256>>>(KP12, bs[1], 0, nullptr, WO1);
    k_bnstats<<<NN, 128>>>(bg[1], bb[1]);

    /* layer 2 (BN fused into agg load) */
    k_agg_s<HID, 4><<<dim3(1, 4, MBATCH), 256, AGG_SMEM>>>((const float*)nullptr, KP12);
    k_gemm<<<ROWS / 128, 256>>>(KP12, bs[2], 0, nullptr, WO2);
    k_bnstats<<<NN, 128>>>(bg[2], bb[2]);

    /* final MLP */
    k_bnapply<<<ROWS * HID / 4 / 256, 256>>>();
    k_gemm<<<ROWS / 128, 256>>>(HID, b1, 1, nullptr, WO3);
    k_bnstats<<<NN, 128>>>(bfg, bfb);
    k_bnapply<<<ROWS * HID / 4 / 256, 256>>>();
    k_gemm<<<ROWS / 128, 256>>>(HID, b2, 1, (float*)d_out, WO4);
}

// round 7
// speedup vs baseline: 2.5866x; 2.5866x over previous
#include <cuda_runtime.h>
#include <cuda_fp16.h>

#define MBATCH 32
#define ET 4
#define NN 512
#define IN0 64
#define HID 128
#define ROWS (MBATCH*NN)      /* 16384 */
#define MAXNBR 64
#define KP0 336               /* pad(5*64+4, 16)  */
#define KP12 656              /* pad(5*128+4, 16) */
#define EPSV 1e-5f

/* weight-concat row offsets inside g_W */
#define WO0 0
#define WO1 336
#define WO2 992
#define WO3 1648
#define WO4 1776
#define WROWS 1904

/* ---------------- static device scratch (no allocation) ---------------- */
__device__ float          g_inv[MBATCH*NN];
__device__ unsigned short g_nbr[MBATCH*ET*NN*MAXNBR];
__device__ int            g_cnt[MBATCH*ET*NN];              // clamped
__device__ int            g_cntfull[MBATCH*ET*NN];          // exact
__device__ float          g_A[ROWS*KP12];
__device__ float          g_W[WROWS*HID];
__device__ float          g_pre[ROWS*HID];
__device__ float          g_h[ROWS*HID];
__device__ __half         g_h16[ROWS*HID];
__device__ float          g_scale[NN];
__device__ float          g_shift[NN];

__device__ __forceinline__ float f2tf(float x) {
    unsigned r;
    asm("cvt.rna.tf32.f32 %0, %1;" : "=r"(r) : "f"(x));
    return __uint_as_float(r);
}

template<int V> __device__ __forceinline__ void ldvec(float* t, const float* p);
template<> __device__ __forceinline__ void ldvec<4>(float* t, const float* p) {
    float4 v = *(const float4*)p; t[0]=v.x; t[1]=v.y; t[2]=v.z; t[3]=v.w;
}
template<> __device__ __forceinline__ void ldvec<2>(float* t, const float* p) {
    float2 v = *(const float2*)p; t[0]=v.x; t[1]=v.y;
}
template<int V> __device__ __forceinline__ void stvec(float* p, const float* t);
template<> __device__ __forceinline__ void stvec<4>(float* p, const float* t) {
    float4 v; v.x=t[0]; v.y=t[1]; v.z=t[2]; v.w=t[3]; *(float4*)p = v;
}
template<> __device__ __forceinline__ void stvec<2>(float* p, const float* t) {
    float2 v; v.x=t[0]; v.y=t[1]; *(float2*)p = v;
}
/* 4 halfs -> 4 floats (one 8-byte load) */
__device__ __forceinline__ void ldvec_h4(float* t, const __half* p) {
    uint2 u = *(const uint2*)p;
    __half2 h0 = *(__half2*)&u.x, h1 = *(__half2*)&u.y;
    float2 f0 = __half22float2(h0), f1 = __half22float2(h1);
    t[0] = f0.x; t[1] = f0.y; t[2] = f1.x; t[3] = f1.y;
}

/* ------------- 1) CSR build: one warp per (b,e,n) row, float4 reads ----- */
__global__ void k_csr(const float* __restrict__ adj) {
    int row  = blockIdx.x * 8 + (threadIdx.x >> 5);
    int lane = threadIdx.x & 31;
    int n    = row & (NN - 1);
    const float4* p = (const float4*)(adj + (size_t)row * NN);
    unsigned short* out = g_nbr + (size_t)row * MAXNBR;
    int cnt = 0;
    for (int it = 0; it < NN / 128; it++) {
        float4 v = p[it * 32 + lane];
        int mb = (it * 32 + lane) * 4;
        float vc[4] = {v.x, v.y, v.z, v.w};
#pragma unroll
        for (int c = 0; c < 4; c++) {
            bool pr = (vc[c] != 0.f) && (mb + c != n);
            unsigned msk = __ballot_sync(0xffffffffu, pr);
            if (pr) {
                int pos = cnt + __popc(msk & ((1u << lane) - 1u));
                if (pos < MAXNBR) out[pos] = (unsigned short)(mb + c);
            }
            cnt += __popc(msk);
        }
    }
    if (lane == 0) {
        g_cnt[row]     = cnt < MAXNBR ? cnt : MAXNBR;
        g_cntfull[row] = cnt;
    }
}

/* ------------- 2) inv degree from exact counts (adj symmetric, 0/1) ---- */
__global__ void k_deg() {
    int i = blockIdx.x * 256 + threadIdx.x;   // b*512+m
    int b = i >> 9, m = i & 511;
    int d = 0;
#pragma unroll
    for (int e = 0; e < ET; e++) d += g_cntfull[((b * ET + e) << 9) + m];
    g_inv[i] = d > 0 ? 1.f / (float)d : 0.f;
}

/* ------------- 3) ALL weight prep in one kernel, tf32-rounded ---------- */
__global__ void k_wprep_all(
    const float* __restrict__ ws0, const float* __restrict__ we0, const float* __restrict__ be0,
    const float* __restrict__ ws1, const float* __restrict__ we1, const float* __restrict__ be1,
    const float* __restrict__ ws2, const float* __restrict__ we2, const float* __restrict__ be2,
    const float* __restrict__ w1,  const float* __restrict__ w2) {
    int idx = blockIdx.x * 256 + threadIdx.x;
    if (idx >= WROWS * HID) return;
    int k = idx >> 7, o = idx & 127;
    float v = 0.f;
    if (k < WO1) {                       /* layer0: IN=64, KP=336 */
        int kk = k;
        if (kk < 64)       v = ws0[kk * HID + o];
        else if (kk < 320) { int e = (kk - 64) >> 6, j = (kk - 64) & 63;
                             v = we0[j * (HID * ET) + o * ET + e]; }
        else if (kk < 324)   v = be0[o * ET + (kk - 320)];
    } else if (k < WO2) {                /* layer1: IN=128, KP=656 */
        int kk = k - WO1;
        if (kk < 128)      v = ws1[kk * HID + o];
        else if (kk < 640) { int e = (kk - 128) >> 7, j = (kk - 128) & 127;
                             v = we1[j * (HID * ET) + o * ET + e]; }
        else if (kk < 644)   v = be1[o * ET + (kk - 640)];
    } else if (k < WO3) {                /* layer2 */
        int kk = k - WO2;
        if (kk < 128)      v = ws2[kk * HID + o];
        else if (kk < 640) { int e = (kk - 128) >> 7, j = (kk - 128) & 127;
                             v = we2[j * (HID * ET) + o * ET + e]; }
        else if (kk < 644)   v = be2[o * ET + (kk - 640)];
    } else if (k < WO4) {
        v = w1[(k - WO3) * HID + o];
    } else {
        v = w2[(k - WO4) * HID + o];
    }
    g_W[k * HID + o] = f2tf(v);
}

/* ------------- 4) sparse aggregation (direct gather, warp = edge type) - */
/* A row r=b*512+n : [ h(b,n,:) | t_e0..3 | s_e0..3 | 0-pad ]  (tf32)      */
/* HSRC: gather from fp16-staged features (layers 1-2, post-ReLU >= 0)     */
template<int IN, bool HSRC>
__global__ void __launch_bounds__(128) k_agg_v(const float* __restrict__ hx, int KP) {
    constexpr int VEC = IN / 32;   // 4 for IN=128, 2 for IN=64
    const float* hf = HSRC ? (const float*)g_h : hx;
    int r = blockIdx.x, b = r >> 9, n = r & 511;
    int warp = threadIdx.x >> 5, lane = threadIdx.x & 31;
    float* Arow = g_A + (size_t)r * KP;
    const float* __restrict__ invb = g_inv + b * NN;

    if (warp == 0) {   /* self-feature copy (fp32 source) */
        float t[VEC];
        ldvec<VEC>(t, hf + (size_t)r * IN + lane * VEC);
#pragma unroll
        for (int c = 0; c < VEC; c++) t[c] = f2tf(t[c]);
        stvec<VEC>(Arow + lane * VEC, t);
    }
    if (warp == 1) {   /* zero-pad tail */
        for (int k = 5 * IN + 4 + lane; k < KP; k += 32) Arow[k] = 0.f;
    }

    int e = warp;
    int lidx = ((b * ET + e) << 9) + n;
    int cnt = g_cnt[lidx];
    const unsigned short* nb = g_nbr + (size_t)lidx * MAXNBR;
    const float*  hb  = hf + (size_t)b * NN * IN + lane * VEC;
    const __half* hb16 = (const __half*)g_h16 + (size_t)b * NN * IN + lane * VEC;

    float acc[VEC];
#pragma unroll
    for (int c = 0; c < VEC; c++) acc[c] = 0.f;
    float s = 0.f;

    int i = 0;
    for (; i + 4 <= cnt; i += 4) {
        int m0 = nb[i], m1 = nb[i+1], m2 = nb[i+2], m3 = nb[i+3];
        float w0 = invb[m0], w1 = invb[m1], w2 = invb[m2], w3 = invb[m3];
        s += (w0 + w1) + (w2 + w3);
        float v0[VEC], v1[VEC], v2[VEC], v3[VEC];
        if (HSRC) {
            ldvec_h4(v0, hb16 + (size_t)m0 * IN);
            ldvec_h4(v1, hb16 + (size_t)m1 * IN);
            ldvec_h4(v2, hb16 + (size_t)m2 * IN);
            ldvec_h4(v3, hb16 + (size_t)m3 * IN);
        } else {
            ldvec<VEC>(v0, hb + (size_t)m0 * IN);
            ldvec<VEC>(v1, hb + (size_t)m1 * IN);
            ldvec<VEC>(v2, hb + (size_t)m2 * IN);
            ldvec<VEC>(v3, hb + (size_t)m3 * IN);
        }
#pragma unroll
        for (int c = 0; c < VEC; c++)
            acc[c] += w0 * v0[c] + w1 * v1[c] + w2 * v2[c] + w3 * v3[c];
    }
    for (; i < cnt; i++) {
        int m = nb[i];
        float w = invb[m];
        s += w;
        float v[VEC];
        if (HSRC) ldvec_h4(v, hb16 + (size_t)m * IN);
        else      ldvec<VEC>(v, hb + (size_t)m * IN);
#pragma unroll
        for (int c = 0; c < VEC; c++) acc[c] += w * v[c];
    }

#pragma unroll
    for (int c = 0; c < VEC; c++) acc[c] = f2tf(acc[c]);
    stvec<VEC>(Arow + IN + e * IN + lane * VEC, acc);
    if (lane == 0) Arow[5 * IN + e] = f2tf(s);
}

/* ------------- 5) TF32 GEMM: 128x128 tile, 256 thr, cp.async 2-stage --- */
#define SAW 24
#define SBW 136

__device__ __forceinline__ unsigned smaddr(const void* p) {
    return (unsigned)__cvta_generic_to_shared(p);
}
__device__ __forceinline__ void cpasync16(unsigned s, const void* g) {
    asm volatile("cp.async.cg.shared.global [%0], [%1], 16;\n" :: "r"(s), "l"(g));
}

__global__ void __launch_bounds__(256) k_gemm(int KP, const float* __restrict__ bias,
                                              int srcH, float* __restrict__ Cout,
                                              int wofs) {
    const float* A = srcH ? (const float*)g_h : (const float*)g_A;
    const float* W = (const float*)g_W + (size_t)wofs * HID;
    float* C = Cout ? Cout : (float*)g_pre;

    __shared__ float sA[2][128 * SAW];
    __shared__ float sB[2][16 * SBW];

    int tid = threadIdx.x;
    int lane = tid & 31, warp = tid >> 5;
    int wm = (warp >> 1) * 32, wn = (warp & 1) * 64;
    int grp = lane >> 2, qid = lane & 3;
    int rowbase = blockIdx.x * 128;
    int KB = KP >> 4;

    float acc[2][8][4];
#pragma unroll
    for (int a = 0; a < 2; a++)
#pragma unroll
        for (int bq = 0; bq < 8; bq++)
#pragma unroll
            for (int c = 0; c < 4; c++) acc[a][bq][c] = 0.f;

    auto issue = [&](int kb, int buf) {
        int kof = kb * 16;
#pragma unroll
        for (int i = 0; i < 2; i++) {
            int t = tid + i * 256, rr = t >> 2, q = t & 3;
            cpasync16(smaddr(&sA[buf][rr * SAW + q * 4]),
                      A + (size_t)(rowbase + rr) * KP + kof + q * 4);
        }
#pragma unroll
        for (int i = 0; i < 2; i++) {
            int t = tid + i * 256, kr = t >> 5, c4 = t & 31;
            cpasync16(smaddr(&sB[buf][kr * SBW + c4 * 4]),
                      W + (size_t)(kof + kr) * HID + c4 * 4);
        }
        asm volatile("cp.async.commit_group;\n" ::);
    };

    issue(0, 0);
    for (int kb = 0; kb < KB; kb++) {
        int buf = kb & 1;
        if (kb + 1 < KB) {
            issue(kb + 1, buf ^ 1);
            asm volatile("cp.async.wait_group 1;\n" ::);
        } else {
            asm volatile("cp.async.wait_group 0;\n" ::);
        }
        __syncthreads();

#pragma unroll
        for (int ks = 0; ks < 2; ks++) {
            int k0 = ks * 8;
            unsigned bf[8][2];
#pragma unroll
            for (int ni = 0; ni < 8; ni++) {
                const float* bp = &sB[buf][(k0 + qid) * SBW + wn + ni * 8 + grp];
                bf[ni][0] = __float_as_uint(bp[0]);
                bf[ni][1] = __float_as_uint(bp[4 * SBW]);
            }
#pragma unroll
            for (int mi = 0; mi < 2; mi++) {
                const float* ap = &sA[buf][(wm + mi * 16 + grp) * SAW + k0 + qid];
                unsigned a0 = __float_as_uint(ap[0]);
                unsigned a1 = __float_as_uint(ap[8 * SAW]);
                unsigned a2 = __float_as_uint(ap[4]);
                unsigned a3 = __float_as_uint(ap[8 * SAW + 4]);
#pragma unroll
                for (int ni = 0; ni < 8; ni++) {
                    asm volatile(
                        "mma.sync.aligned.m16n8k8.row.col.f32.tf32.tf32.f32 "
                        "{%0,%1,%2,%3}, {%4,%5,%6,%7}, {%8,%9}, {%0,%1,%2,%3};\n"
                        : "+f"(acc[mi][ni][0]), "+f"(acc[mi][ni][1]),
                          "+f"(acc[mi][ni][2]), "+f"(acc[mi][ni][3])
                        : "r"(a0), "r"(a1), "r"(a2), "r"(a3),
                          "r"(bf[ni][0]), "r"(bf[ni][1]));
                }
            }
        }
        __syncthreads();
    }

#pragma unroll
    for (int mi = 0; mi < 2; mi++) {
        int row = rowbase + wm + mi * 16 + grp;
#pragma unroll
        for (int ni = 0; ni < 8; ni++) {
            int col = wn + ni * 8 + qid * 2;
            float b0 = bias[col], b1 = bias[col + 1];
            C[(size_t)row * HID + col]           = acc[mi][ni][0] + b0;
            C[(size_t)row * HID + col + 1]       = acc[mi][ni][1] + b1;
            C[(size_t)(row + 8) * HID + col]     = acc[mi][ni][2] + b0;
            C[(size_t)(row + 8) * HID + col + 1] = acc[mi][ni][3] + b1;
        }
    }
}

/* ------------- 6) BN stats per node (single pass: sum, sumsq) ---------- */
__global__ void k_bnstats(const float* __restrict__ g, const float* __restrict__ bb) {
    int n = blockIdx.x, o = threadIdx.x;
    const float* pre = (const float*)g_pre;
    __shared__ float rs[128], rq[128];
    float s = 0.f, q = 0.f;
    for (int b = 0; b < MBATCH; b++) {
        float v = pre[(size_t)(b * NN + n) * HID + o];
        s += v;
        q += v * v;
    }
    rs[o] = s; rq[o] = q; __syncthreads();
    for (int st = 64; st > 0; st >>= 1) {
        if (o < st) { rs[o] += rs[o + st]; rq[o] += rq[o + st]; }
        __syncthreads();
    }
    if (o == 0) {
        float mean = rs[0] * (1.f / (MBATCH * HID));
        float var  = rq[0] * (1.f / (MBATCH * HID)) - mean * mean;
        if (var < 0.f) var = 0.f;
        float sc = g[n] * rsqrtf(var + EPSV);
        g_scale[n] = sc;
        g_shift[n] = bb[n] - mean * sc;
    }
}

/* ------------- 7) BN apply + ReLU: fp32(tf32) + fp16 staged copies ----- */
__global__ void k_bnapply() {
    int i4 = blockIdx.x * 256 + threadIdx.x;     // over ROWS*HID/4
    float4 v = ((const float4*)g_pre)[i4];
    int r = i4 >> 5;            // HID/4 = 32 float4 per row
    int n = r & 511;
    float sc = g_scale[n], sh = g_shift[n];
    float x0 = fmaxf(v.x * sc + sh, 0.f);
    float x1 = fmaxf(v.y * sc + sh, 0.f);
    float x2 = fmaxf(v.z * sc + sh, 0.f);
    float x3 = fmaxf(v.w * sc + sh, 0.f);
    float4 o; o.x = f2tf(x0); o.y = f2tf(x1); o.z = f2tf(x2); o.w = f2tf(x3);
    ((float4*)g_h)[i4] = o;
    __half2 h0 = __floats2half2_rn(x0, x1);
    __half2 h1 = __floats2half2_rn(x2, x3);
    uint2 u; u.x = *(unsigned*)&h0; u.y = *(unsigned*)&h1;
    ((uint2*)g_h16)[i4] = u;
}

/* ---------------- driver ------------------------------------------------ */
extern "C" void kernel_launch(void* const* d_in, const int* in_sizes, int n_in,
                              void* d_out, int out_size) {
    const float* x   = (const float*)d_in[0];
    const float* adj = (const float*)d_in[1];
    const float* ws[3] = {(const float*)d_in[2],  (const float*)d_in[8],  (const float*)d_in[14]};
    const float* bs[3] = {(const float*)d_in[3],  (const float*)d_in[9],  (const float*)d_in[15]};
    const float* we[3] = {(const float*)d_in[4],  (const float*)d_in[10], (const float*)d_in[16]};
    const float* be[3] = {(const float*)d_in[5],  (const float*)d_in[11], (const float*)d_in[17]};
    const float* bg[3] = {(const float*)d_in[6],  (const float*)d_in[12], (const float*)d_in[18]};
    const float* bb[3] = {(const float*)d_in[7],  (const float*)d_in[13], (const float*)d_in[19]};
    const float* w1  = (const float*)d_in[20];
    const float* b1  = (const float*)d_in[21];
    const float* bfg = (const float*)d_in[22];
    const float* bfb = (const float*)d_in[23];
    const float* w2  = (const float*)d_in[24];
    const float* b2  = (const float*)d_in[25];

    (void)in_sizes; (void)n_in; (void)out_size;

    k_csr<<<(MBATCH * ET * NN) / 8, 256>>>(adj);
    k_deg<<<(MBATCH * NN) / 256, 256>>>();
    k_wprep_all<<<(WROWS * HID + 255) / 256, 256>>>(
        ws[0], we[0], be[0], ws[1], we[1], be[1], ws[2], we[2], be[2], w1, w2);

    /* layer 0: gather fp32 x */
    k_agg_v<IN0, false><<<ROWS, 128>>>(x, KP0);
    k_gemm<<<ROWS / 128, 256>>>(KP0, bs[0], 0, nullptr, WO0);
    k_bnstats<<<NN, 128>>>(bg[0], bb[0]);
    k_bnapply<<<ROWS * HID / 4 / 256, 256>>>();

    /* layer 1: gather fp16-staged h */
    k_agg_v<HID, true><<<ROWS, 128>>>((const float*)nullptr, KP12);
    k_gemm<<<ROWS / 128, 256>>>(KP12, bs[1], 0, nullptr, WO1);
    k_bnstats<<<NN, 128>>>(bg[1], bb[1]);
    k_bnapply<<<ROWS * HID / 4 / 256, 256>>>();

    /* layer 2 */
    k_agg_v<HID, true><<<ROWS, 128>>>((const float*)nullptr, KP12);
    k_gemm<<<ROWS / 128, 256>>>(KP12, bs[2], 0, nullptr, WO2);
    k_bnstats<<<NN, 128>>>(bg[2], bb[2]);
    k_bnapply<<<ROWS * HID / 4 / 256, 256>>>();

    /* final MLP */
    k_gemm<<<ROWS / 128, 256>>>(HID, b1, 1, nullptr, WO3);
    k_bnstats<<<NN, 128>>>(bfg, bfb);
    k_bnapply<<<ROWS * HID / 4 / 256, 256>>>();
    k_gemm<<<ROWS / 128, 256>>>(HID, b2, 1, (float*)d_out, WO4);
}

// round 8
// speedup vs baseline: 2.9063x; 1.1236x over previous
#include <cuda_runtime.h>
#include <cuda_fp16.h>

#define MBATCH 32
#define ET 4
#define NN 512
#define IN0 64
#define HID 128
#define ROWS (MBATCH*NN)      /* 16384 */
#define MAXNBR 64
#define KP0 336               /* pad(5*64+4, 16)  */
#define KP12 656              /* pad(5*128+4, 16) */
#define EPSV 1e-5f

/* weight-concat row offsets inside g_W */
#define WO0 0
#define WO1 336
#define WO2 992
#define WO3 1648
#define WO4 1776
#define WROWS 1904

/* ---------------- static device scratch (no allocation) ---------------- */
__device__ float          g_inv[MBATCH*NN];
__device__ float          g_ssum[MBATCH*ET*NN];
__device__ unsigned short g_nbr[MBATCH*ET*NN*MAXNBR];
__device__ int            g_cnt[MBATCH*ET*NN];              // clamped
__device__ int            g_cntfull[MBATCH*ET*NN];          // exact
__device__ float          g_A[ROWS*KP12];
__device__ float          g_W[WROWS*HID];
__device__ float          g_pre[ROWS*HID];
__device__ float          g_h[ROWS*HID];
__device__ __half         g_h16[ROWS*HID];                  // inv-scaled, fp16
__device__ __half         g_x16[MBATCH*NN*IN0];             // inv-scaled x, fp16
__device__ float          g_bnsum[4*NN];
__device__ float          g_bnsq[4*NN];

__device__ __forceinline__ float f2tf(float x) {
    unsigned r;
    asm("cvt.rna.tf32.f32 %0, %1;" : "=r"(r) : "f"(x));
    return __uint_as_float(r);
}

/* ------------- 1) CSR build: one warp per (b,e,n) row, float4 reads ----- */
__global__ void k_csr(const float* __restrict__ adj) {
    int row  = blockIdx.x * 8 + (threadIdx.x >> 5);
    int lane = threadIdx.x & 31;
    int n    = row & (NN - 1);
    const float4* p = (const float4*)(adj + (size_t)row * NN);
    unsigned short* out = g_nbr + (size_t)row * MAXNBR;
    int cnt = 0;
    for (int it = 0; it < NN / 128; it++) {
        float4 v = p[it * 32 + lane];
        int mb = (it * 32 + lane) * 4;
        float vc[4] = {v.x, v.y, v.z, v.w};
#pragma unroll
        for (int c = 0; c < 4; c++) {
            bool pr = (vc[c] != 0.f) && (mb + c != n);
            unsigned msk = __ballot_sync(0xffffffffu, pr);
            if (pr) {
                int pos = cnt + __popc(msk & ((1u << lane) - 1u));
                if (pos < MAXNBR) out[pos] = (unsigned short)(mb + c);
            }
            cnt += __popc(msk);
        }
    }
    if (lane == 0) {
        g_cnt[row]     = cnt < MAXNBR ? cnt : MAXNBR;
        g_cntfull[row] = cnt;
    }
}

/* ------------- 2) inv degree from exact counts (adj symmetric, 0/1) ---- */
__global__ void k_deg() {
    int i = blockIdx.x * 256 + threadIdx.x;   // b*512+m
    int b = i >> 9, m = i & 511;
    int d = 0;
#pragma unroll
    for (int e = 0; e < ET; e++) d += g_cntfull[((b * ET + e) << 9) + m];
    g_inv[i] = d > 0 ? 1.f / (float)d : 0.f;
}

/* ------------- 3) per-row sum of inv over neighbors (layer-invariant) -- */
__global__ void k_ssum() {
    int lidx = blockIdx.x * 256 + threadIdx.x;
    int b = lidx >> 11;
    int cnt = g_cnt[lidx];
    const unsigned short* nb = g_nbr + (size_t)lidx * MAXNBR;
    const float* invb = g_inv + b * NN;
    float s = 0.f;
    for (int i = 0; i < cnt; i++) s += invb[nb[i]];
    g_ssum[lidx] = s;
}

/* ------------- 4) stage inv-scaled x as fp16 --------------------------- */
__global__ void k_stage0(const float* __restrict__ x) {
    int i4 = blockIdx.x * 256 + threadIdx.x;   // over MB*NN*IN0/4
    float4 v = ((const float4*)x)[i4];
    int r = i4 >> 4;                            // IN0/4 = 16 float4 per row
    float w = g_inv[r];
    __half2 h0 = __floats2half2_rn(w * v.x, w * v.y);
    __half2 h1 = __floats2half2_rn(w * v.z, w * v.w);
    uint2 u; u.x = *(unsigned*)&h0; u.y = *(unsigned*)&h1;
    ((uint2*)g_x16)[i4] = u;
}

/* ------------- 5) ALL weight prep + BN-stat zeroing -------------------- */
__global__ void k_wprep_all(
    const float* __restrict__ ws0, const float* __restrict__ we0, const float* __restrict__ be0,
    const float* __restrict__ ws1, const float* __restrict__ we1, const float* __restrict__ be1,
    const float* __restrict__ ws2, const float* __restrict__ we2, const float* __restrict__ be2,
    const float* __restrict__ w1,  const float* __restrict__ w2) {
    int idx = blockIdx.x * 256 + threadIdx.x;
    if (idx < 4 * NN) { g_bnsum[idx] = 0.f; g_bnsq[idx] = 0.f; }
    if (idx >= WROWS * HID) return;
    int k = idx >> 7, o = idx & 127;
    float v = 0.f;
    if (k < WO1) {                       /* layer0: IN=64, KP=336 */
        int kk = k;
        if (kk < 64)       v = ws0[kk * HID + o];
        else if (kk < 320) { int e = (kk - 64) >> 6, j = (kk - 64) & 63;
                             v = we0[j * (HID * ET) + o * ET + e]; }
        else if (kk < 324)   v = be0[o * ET + (kk - 320)];
    } else if (k < WO2) {                /* layer1: IN=128, KP=656 */
        int kk = k - WO1;
        if (kk < 128)      v = ws1[kk * HID + o];
        else if (kk < 640) { int e = (kk - 128) >> 7, j = (kk - 128) & 127;
                             v = we1[j * (HID * ET) + o * ET + e]; }
        else if (kk < 644)   v = be1[o * ET + (kk - 640)];
    } else if (k < WO3) {                /* layer2 */
        int kk = k - WO2;
        if (kk < 128)      v = ws2[kk * HID + o];
        else if (kk < 640) { int e = (kk - 128) >> 7, j = (kk - 128) & 127;
                             v = we2[j * (HID * ET) + o * ET + e]; }
        else if (kk < 644)   v = be2[o * ET + (kk - 640)];
    } else if (k < WO4) {
        v = w1[(k - WO3) * HID + o];
    } else {
        v = w2[(k - WO4) * HID + o];
    }
    g_W[k * HID + o] = f2tf(v);
}

/* ------------- 6) sparse aggregation: pure-sum gather of fp16 ---------- */
/* A row r=b*512+n : [ h(b,n,:) | t_e0..3 | s_e0..3 | 0-pad ]  (tf32)      */
template<int IN>
__global__ void __launch_bounds__(128) k_agg(const float* __restrict__ selfx, int KP) {
    constexpr int VEC = IN / 32;   // 4 for IN=128, 2 for IN=64
    const __half* __restrict__ h16 = (IN == IN0) ? (const __half*)g_x16
                                                 : (const __half*)g_h16;
    const float* __restrict__ sf = selfx ? selfx : (const float*)g_h;
    int r = blockIdx.x, b = r >> 9, n = r & 511;
    int warp = threadIdx.x >> 5, lane = threadIdx.x & 31;
    float* Arow = g_A + (size_t)r * KP;

    if (warp == 0) {   /* self-feature copy (fp32 source, tf32-round) */
#pragma unroll
        for (int c = 0; c < VEC; c++)
            Arow[lane * VEC + c] = f2tf(sf[(size_t)r * IN + lane * VEC + c]);
    }
    if (warp == 1) {   /* s-values + zero-pad tail */
        if (lane < ET)
            Arow[5 * IN + lane] = f2tf(g_ssum[((b * ET + lane) << 9) + n]);
        for (int k = 5 * IN + 4 + lane; k < KP; k += 32) Arow[k] = 0.f;
    }

    int e = warp;
    int lidx = ((b * ET + e) << 9) + n;
    int cnt = g_cnt[lidx];
    const unsigned short* nb = g_nbr + (size_t)lidx * MAXNBR;
    const __half* hb = h16 + (size_t)b * NN * IN + lane * VEC;

    float acc[VEC];
#pragma unroll
    for (int c = 0; c < VEC; c++) acc[c] = 0.f;

    int i = 0;
    for (; i + 4 <= cnt; i += 4) {
        uint2 q4 = *(const uint2*)(nb + i);           /* 4 packed u16 indices */
        int m0 = q4.x & 0xffff, m1 = q4.x >> 16;
        int m2 = q4.y & 0xffff, m3 = q4.y >> 16;
        if (VEC == 4) {
            uint2 f0 = *(const uint2*)(hb + (size_t)m0 * IN);
            uint2 f1 = *(const uint2*)(hb + (size_t)m1 * IN);
            uint2 f2 = *(const uint2*)(hb + (size_t)m2 * IN);
            uint2 f3 = *(const uint2*)(hb + (size_t)m3 * IN);
            float2 a, bb2;
            a = __half22float2(*(__half2*)&f0.x); bb2 = __half22float2(*(__half2*)&f0.y);
            acc[0] += a.x; acc[1] += a.y; acc[2] += bb2.x; acc[3] += bb2.y;
            a = __half22float2(*(__half2*)&f1.x); bb2 = __half22float2(*(__half2*)&f1.y);
            acc[0] += a.x; acc[1] += a.y; acc[2] += bb2.x; acc[3] += bb2.y;
            a = __half22float2(*(__half2*)&f2.x); bb2 = __half22float2(*(__half2*)&f2.y);
            acc[0] += a.x; acc[1] += a.y; acc[2] += bb2.x; acc[3] += bb2.y;
            a = __half22float2(*(__half2*)&f3.x); bb2 = __half22float2(*(__half2*)&f3.y);
            acc[0] += a.x; acc[1] += a.y; acc[2] += bb2.x; acc[3] += bb2.y;
        } else {
            unsigned f0 = *(const unsigned*)(hb + (size_t)m0 * IN);
            unsigned f1 = *(const unsigned*)(hb + (size_t)m1 * IN);
            unsigned f2 = *(const unsigned*)(hb + (size_t)m2 * IN);
            unsigned f3 = *(const unsigned*)(hb + (size_t)m3 * IN);
            float2 a;
            a = __half22float2(*(__half2*)&f0); acc[0] += a.x; acc[1] += a.y;
            a = __half22float2(*(__half2*)&f1); acc[0] += a.x; acc[1] += a.y;
            a = __half22float2(*(__half2*)&f2); acc[0] += a.x; acc[1] += a.y;
            a = __half22float2(*(__half2*)&f3); acc[0] += a.x; acc[1] += a.y;
        }
    }
    for (; i < cnt; i++) {
        int m = nb[i];
        if (VEC == 4) {
            uint2 f0 = *(const uint2*)(hb + (size_t)m * IN);
            float2 a = __half22float2(*(__half2*)&f0.x);
            float2 bb2 = __half22float2(*(__half2*)&f0.y);
            acc[0] += a.x; acc[1] += a.y; acc[2] += bb2.x; acc[3] += bb2.y;
        } else {
            unsigned f0 = *(const unsigned*)(hb + (size_t)m * IN);
            float2 a = __half22float2(*(__half2*)&f0);
            acc[0] += a.x; acc[1] += a.y;
        }
    }

#pragma unroll
    for (int c = 0; c < VEC; c++)
        Arow[IN + e * IN + lane * VEC + c] = f2tf(acc[c]);
}

/* ------------- 7) TF32 GEMM + fused BN-stat accumulation --------------- */
#define SAW 24
#define SBW 136

__device__ __forceinline__ unsigned smaddr(const void* p) {
    return (unsigned)__cvta_generic_to_shared(p);
}
__device__ __forceinline__ void cpasync16(unsigned s, const void* g) {
    asm volatile("cp.async.cg.shared.global [%0], [%1], 16;\n" :: "r"(s), "l"(g));
}

__global__ void __launch_bounds__(256) k_gemm(int KP, const float* __restrict__ bias,
                                              int srcH, float* __restrict__ Cout,
                                              int wofs, int sb) {
    const float* A = srcH ? (const float*)g_h : (const float*)g_A;
    const float* W = (const float*)g_W + (size_t)wofs * HID;
    float* C = Cout ? Cout : (float*)g_pre;

    __shared__ float sA[2][128 * SAW];
    __shared__ float sB[2][16 * SBW];

    int tid = threadIdx.x;
    int lane = tid & 31, warp = tid >> 5;
    int wm = (warp >> 1) * 32, wn = (warp & 1) * 64;
    int grp = lane >> 2, qid = lane & 3;
    int rowbase = blockIdx.x * 128;
    int KB = KP >> 4;

    float acc[2][8][4];
#pragma unroll
    for (int a = 0; a < 2; a++)
#pragma unroll
        for (int bq = 0; bq < 8; bq++)
#pragma unroll
            for (int c = 0; c < 4; c++) acc[a][bq][c] = 0.f;

    auto issue = [&](int kb, int buf) {
        int kof = kb * 16;
#pragma unroll
        for (int i = 0; i < 2; i++) {
            int t = tid + i * 256, rr = t >> 2, q = t & 3;
            cpasync16(smaddr(&sA[buf][rr * SAW + q * 4]),
                      A + (size_t)(rowbase + rr) * KP + kof + q * 4);
        }
#pragma unroll
        for (int i = 0; i < 2; i++) {
            int t = tid + i * 256, kr = t >> 5, c4 = t & 31;
            cpasync16(smaddr(&sB[buf][kr * SBW + c4 * 4]),
                      W + (size_t)(kof + kr) * HID + c4 * 4);
        }
        asm volatile("cp.async.commit_group;\n" ::);
    };

    issue(0, 0);
    for (int kb = 0; kb < KB; kb++) {
        int buf = kb & 1;
        if (kb + 1 < KB) {
            issue(kb + 1, buf ^ 1);
            asm volatile("cp.async.wait_group 1;\n" ::);
        } else {
            asm volatile("cp.async.wait_group 0;\n" ::);
        }
        __syncthreads();

#pragma unroll
        for (int ks = 0; ks < 2; ks++) {
            int k0 = ks * 8;
            unsigned bf[8][2];
#pragma unroll
            for (int ni = 0; ni < 8; ni++) {
                const float* bp = &sB[buf][(k0 + qid) * SBW + wn + ni * 8 + grp];
                bf[ni][0] = __float_as_uint(bp[0]);
                bf[ni][1] = __float_as_uint(bp[4 * SBW]);
            }
#pragma unroll
            for (int mi = 0; mi < 2; mi++) {
                const float* ap = &sA[buf][(wm + mi * 16 + grp) * SAW + k0 + qid];
                unsigned a0 = __float_as_uint(ap[0]);
                unsigned a1 = __float_as_uint(ap[8 * SAW]);
                unsigned a2 = __float_as_uint(ap[4]);
                unsigned a3 = __float_as_uint(ap[8 * SAW + 4]);
#pragma unroll
                for (int ni = 0; ni < 8; ni++) {
                    asm volatile(
                        "mma.sync.aligned.m16n8k8.row.col.f32.tf32.tf32.f32 "
                        "{%0,%1,%2,%3}, {%4,%5,%6,%7}, {%8,%9}, {%0,%1,%2,%3};\n"
                        : "+f"(acc[mi][ni][0]), "+f"(acc[mi][ni][1]),
                          "+f"(acc[mi][ni][2]), "+f"(acc[mi][ni][3])
                        : "r"(a0), "r"(a1), "r"(a2), "r"(a3),
                          "r"(bf[ni][0]), "r"(bf[ni][1]));
                }
            }
        }
        __syncthreads();
    }

    /* epilogue: +bias, store, per-row BN partial sums */
    float rs[2][2] = {{0.f,0.f},{0.f,0.f}};
    float rq[2][2] = {{0.f,0.f},{0.f,0.f}};
#pragma unroll
    for (int mi = 0; mi < 2; mi++) {
        int row = rowbase + wm + mi * 16 + grp;
#pragma unroll
        for (int ni = 0; ni < 8; ni++) {
            int col = wn + ni * 8 + qid * 2;
            float b0 = bias[col], b1 = bias[col + 1];
            float v0 = acc[mi][ni][0] + b0, v1 = acc[mi][ni][1] + b1;
            float v2 = acc[mi][ni][2] + b0, v3 = acc[mi][ni][3] + b1;
            C[(size_t)row * HID + col]           = v0;
            C[(size_t)row * HID + col + 1]       = v1;
            C[(size_t)(row + 8) * HID + col]     = v2;
            C[(size_t)(row + 8) * HID + col + 1] = v3;
            rs[mi][0] += v0 + v1; rq[mi][0] += v0 * v0 + v1 * v1;
            rs[mi][1] += v2 + v3; rq[mi][1] += v2 * v2 + v3 * v3;
        }
    }
    if (sb >= 0) {
#pragma unroll
        for (int mi = 0; mi < 2; mi++)
#pragma unroll
            for (int rr = 0; rr < 2; rr++) {
                rs[mi][rr] += __shfl_xor_sync(0xffffffffu, rs[mi][rr], 1);
                rs[mi][rr] += __shfl_xor_sync(0xffffffffu, rs[mi][rr], 2);
                rq[mi][rr] += __shfl_xor_sync(0xffffffffu, rq[mi][rr], 1);
                rq[mi][rr] += __shfl_xor_sync(0xffffffffu, rq[mi][rr], 2);
            }
        if (qid == 0) {
#pragma unroll
            for (int mi = 0; mi < 2; mi++)
#pragma unroll
                for (int rr = 0; rr < 2; rr++) {
                    int row = rowbase + wm + mi * 16 + grp + rr * 8;
                    int n = row & 511;
                    atomicAdd(&g_bnsum[sb * NN + n], rs[mi][rr]);
                    atomicAdd(&g_bnsq [sb * NN + n], rq[mi][rr]);
                }
        }
    }
}

/* ------------- 8) BN finalize + apply + ReLU (+ inv-scaled fp16) ------- */
template<bool H16>
__global__ void k_bnapply(const float* __restrict__ g, const float* __restrict__ bb,
                          int sb) {
    int i4 = blockIdx.x * 256 + threadIdx.x;     // over ROWS*HID/4
    float4 v = ((const float4*)g_pre)[i4];
    int r = i4 >> 5;            // 32 float4 per row
    int n = r & 511;
    const float invC = 1.f / (float)(MBATCH * HID);
    float mean = g_bnsum[sb * NN + n] * invC;
    float var  = g_bnsq [sb * NN + n] * invC - mean * mean;
    var = fmaxf(var, 0.f);
    float sc = g[n] * rsqrtf(var + EPSV);
    float sh = bb[n] - mean * sc;
    float x0 = fmaxf(v.x * sc + sh, 0.f);
    float x1 = fmaxf(v.y * sc + sh, 0.f);
    float x2 = fmaxf(v.z * sc + sh, 0.f);
    float x3 = fmaxf(v.w * sc + sh, 0.f);
    float4 o; o.x = f2tf(x0); o.y = f2tf(x1); o.z = f2tf(x2); o.w = f2tf(x3);
    ((float4*)g_h)[i4] = o;
    if (H16) {
        float w = g_inv[r];
        __half2 h0 = __floats2half2_rn(w * x0, w * x1);
        __half2 h1 = __floats2half2_rn(w * x2, w * x3);
        uint2 u; u.x = *(unsigned*)&h0; u.y = *(unsigned*)&h1;
        ((uint2*)g_h16)[i4] = u;
    }
}

/* ---------------- driver ------------------------------------------------ */
extern "C" void kernel_launch(void* const* d_in, const int* in_sizes, int n_in,
                              void* d_out, int out_size) {
    const float* x   = (const float*)d_in[0];
    const float* adj = (const float*)d_in[1];
    const float* ws[3] = {(const float*)d_in[2],  (const float*)d_in[8],  (const float*)d_in[14]};
    const float* bs[3] = {(const float*)d_in[3],  (const float*)d_in[9],  (const float*)d_in[15]};
    const float* we[3] = {(const float*)d_in[4],  (const float*)d_in[10], (const float*)d_in[16]};
    const float* be[3] = {(const float*)d_in[5],  (const float*)d_in[11], (const float*)d_in[17]};
    const float* bg[3] = {(const float*)d_in[6],  (const float*)d_in[12], (const float*)d_in[18]};
    const float* bb[3] = {(const float*)d_in[7],  (const float*)d_in[13], (const float*)d_in[19]};
    const float* w1  = (const float*)d_in[20];
    const float* b1  = (const float*)d_in[21];
    const float* bfg = (const float*)d_in[22];
    const float* bfb = (const float*)d_in[23];
    const float* w2  = (const float*)d_in[24];
    const float* b2  = (const float*)d_in[25];

    (void)in_sizes; (void)n_in; (void)out_size;

    k_csr<<<(MBATCH * ET * NN) / 8, 256>>>(adj);
    k_deg<<<(MBATCH * NN) / 256, 256>>>();
    k_ssum<<<(MBATCH * ET * NN) / 256, 256>>>();
    k_stage0<<<(MBATCH * NN * IN0 / 4) / 256, 256>>>(x);
    k_wprep_all<<<(WROWS * HID + 255) / 256, 256>>>(
        ws[0], we[0], be[0], ws[1], we[1], be[1], ws[2], we[2], be[2], w1, w2);

    /* layer 0 */
    k_agg<IN0><<<ROWS, 128>>>(x, KP0);
    k_gemm<<<ROWS / 128, 256>>>(KP0, bs[0], 0, nullptr, WO0, 0);
    k_bnapply<true><<<ROWS * HID / 4 / 256, 256>>>(bg[0], bb[0], 0);

    /* layer 1 */
    k_agg<HID><<<ROWS, 128>>>((const float*)nullptr, KP12);
    k_gemm<<<ROWS / 128, 256>>>(KP12, bs[1], 0, nullptr, WO1, 1);
    k_bnapply<true><<<ROWS * HID / 4 / 256, 256>>>(bg[1], bb[1], 1);

    /* layer 2 */
    k_agg<HID><<<ROWS, 128>>>((const float*)nullptr, KP12);
    k_gemm<<<ROWS / 128, 256>>>(KP12, bs[2], 0, nullptr, WO2, 2);
    k_bnapply<true><<<ROWS * HID / 4 / 256, 256>>>(bg[2], bb[2], 2);

    /* final MLP */
    k_gemm<<<ROWS / 128, 256>>>(HID, b1, 1, nullptr, WO3, 3);
    k_bnapply<false><<<ROWS * HID / 4 / 256, 256>>>(bfg, bfb, 3);
    k_gemm<<<ROWS / 128, 256>>>(HID, b2, 1, (float*)d_out, WO4, -1);
}

// round 9
// speedup vs baseline: 3.5118x; 1.2083x over previous
#include <cuda_runtime.h>
#include <cuda_fp16.h>

#define MBATCH 32
#define ET 4
#define NN 512
#define IN0 64
#define HID 128
#define ROWS (MBATCH*NN)      /* 16384 */
#define MAXNBR 64
#define KP0 352               /* pad(5*64+4, 32)  */
#define KP12 672              /* pad(5*128+4, 32) */
#define EPSV 1e-5f

/* transposed-weight column offsets inside g_Wt[128][WTCOLS] */
#define WT0 0
#define WT1 352
#define WT2 1024
#define WT3 1696
#define WT4 1824
#define WTCOLS 1952

/* ---------------- static device scratch (no allocation) ---------------- */
__device__ float          g_inv[MBATCH*NN];
__device__ float          g_ssum[MBATCH*ET*NN];
__device__ __align__(16) unsigned short g_nbr[MBATCH*ET*NN*MAXNBR];
__device__ int            g_cnt[MBATCH*ET*NN];              // clamped
__device__ int            g_cntfull[MBATCH*ET*NN];          // exact
__device__ __align__(16) __half g_A[ROWS*KP12];             // 22 MB
__device__ __align__(16) __half g_Wt[HID*WTCOLS];           // 0.5 MB
__device__ __align__(16) float  g_pre[ROWS*HID];            // 8.4 MB
__device__ __align__(16) __half g_hh[ROWS*HID];             // post-BN act, fp16
__device__ __align__(16) __half g_h16[ROWS*HID];            // inv-scaled act
__device__ __align__(16) __half g_x16[MBATCH*NN*IN0];       // inv-scaled x
__device__ float          g_bnsum[4*NN];
__device__ float          g_bnsq[4*NN];

/* ------------- 1) CSR build: one warp per (b,e,n) row, float4 reads ----- */
__global__ void k_csr(const float* __restrict__ adj) {
    int row  = blockIdx.x * 8 + (threadIdx.x >> 5);
    int lane = threadIdx.x & 31;
    int n    = row & (NN - 1);
    const float4* p = (const float4*)(adj + (size_t)row * NN);
    unsigned short* out = g_nbr + (size_t)row * MAXNBR;
    int cnt = 0;
    for (int it = 0; it < NN / 128; it++) {
        float4 v = p[it * 32 + lane];
        int mb = (it * 32 + lane) * 4;
        float vc[4] = {v.x, v.y, v.z, v.w};
#pragma unroll
        for (int c = 0; c < 4; c++) {
            bool pr = (vc[c] != 0.f) && (mb + c != n);
            unsigned msk = __ballot_sync(0xffffffffu, pr);
            if (pr) {
                int pos = cnt + __popc(msk & ((1u << lane) - 1u));
                if (pos < MAXNBR) out[pos] = (unsigned short)(mb + c);
            }
            cnt += __popc(msk);
        }
    }
    if (lane == 0) {
        g_cnt[row]     = cnt < MAXNBR ? cnt : MAXNBR;
        g_cntfull[row] = cnt;
    }
}

/* ------------- 2) inv degree from exact counts (adj symmetric, 0/1) ---- */
__global__ void k_deg() {
    int i = blockIdx.x * 256 + threadIdx.x;
    int b = i >> 9, m = i & 511;
    int d = 0;
#pragma unroll
    for (int e = 0; e < ET; e++) d += g_cntfull[((b * ET + e) << 9) + m];
    g_inv[i] = d > 0 ? 1.f / (float)d : 0.f;
}

/* ------------- 3) per-row sum of inv over neighbors (layer-invariant) -- */
__global__ void k_ssum() {
    int lidx = blockIdx.x * 256 + threadIdx.x;
    int b = lidx >> 11;
    int cnt = g_cnt[lidx];
    const unsigned short* nb = g_nbr + (size_t)lidx * MAXNBR;
    const float* invb = g_inv + b * NN;
    float s = 0.f;
    for (int i = 0; i < cnt; i++) s += invb[nb[i]];
    g_ssum[lidx] = s;
}

/* ------------- 4) stage inv-scaled x as fp16 --------------------------- */
__global__ void k_stage0(const float* __restrict__ x) {
    int i4 = blockIdx.x * 256 + threadIdx.x;
    float4 v = ((const float4*)x)[i4];
    int r = i4 >> 4;
    float w = g_inv[r];
    __half2 h0 = __floats2half2_rn(w * v.x, w * v.y);
    __half2 h1 = __floats2half2_rn(w * v.z, w * v.w);
    uint2 u; u.x = *(unsigned*)&h0; u.y = *(unsigned*)&h1;
    ((uint2*)g_x16)[i4] = u;
}

/* ------------- 5) transposed weight prep (fp16) + BN-stat zeroing ------ */
__global__ void k_wprep_all(
    const float* __restrict__ ws0, const float* __restrict__ we0, const float* __restrict__ be0,
    const float* __restrict__ ws1, const float* __restrict__ we1, const float* __restrict__ be1,
    const float* __restrict__ ws2, const float* __restrict__ we2, const float* __restrict__ be2,
    const float* __restrict__ w1,  const float* __restrict__ w2) {
    int idx = blockIdx.x * 256 + threadIdx.x;
    if (idx < 4 * NN) { g_bnsum[idx] = 0.f; g_bnsq[idx] = 0.f; }
    if (idx >= HID * WTCOLS) return;
    int o = idx / WTCOLS, k = idx - o * WTCOLS;
    float v = 0.f;
    if (k < WT1) {                       /* layer0: IN=64 */
        int kk = k;
        if (kk < 64)       v = ws0[kk * HID + o];
        else if (kk < 320) { int e = (kk - 64) >> 6, j = (kk - 64) & 63;
                             v = we0[j * (HID * ET) + o * ET + e]; }
        else if (kk < 324)   v = be0[o * ET + (kk - 320)];
    } else if (k < WT2) {                /* layer1 */
        int kk = k - WT1;
        if (kk < 128)      v = ws1[kk * HID + o];
        else if (kk < 640) { int e = (kk - 128) >> 7, j = (kk - 128) & 127;
                             v = we1[j * (HID * ET) + o * ET + e]; }
        else if (kk < 644)   v = be1[o * ET + (kk - 640)];
    } else if (k < WT3) {                /* layer2 */
        int kk = k - WT2;
        if (kk < 128)      v = ws2[kk * HID + o];
        else if (kk < 640) { int e = (kk - 128) >> 7, j = (kk - 128) & 127;
                             v = we2[j * (HID * ET) + o * ET + e]; }
        else if (kk < 644)   v = be2[o * ET + (kk - 640)];
    } else if (k < WT4) {
        v = w1[(k - WT3) * HID + o];
    } else {
        v = w2[(k - WT4) * HID + o];
    }
    g_Wt[o * WTCOLS + k] = __float2half_rn(v);
}

/* ------------- 6) sparse aggregation: pure-sum gather, fp16 A out ------ */
template<int IN>
__global__ void __launch_bounds__(128) k_agg(const float* __restrict__ x0, int KP) {
    constexpr int VEC = IN / 32;   // 4 for IN=128, 2 for IN=64
    const __half* __restrict__ h16 = (IN == IN0) ? (const __half*)g_x16
                                                 : (const __half*)g_h16;
    int r = blockIdx.x, b = r >> 9, n = r & 511;
    int warp = threadIdx.x >> 5, lane = threadIdx.x & 31;
    __half* Arow = g_A + (size_t)r * KP;

    if (warp == 0) {   /* self-feature copy */
        if (IN == IN0) {
            float2 v = *(const float2*)(x0 + (size_t)r * IN + lane * 2);
            *(__half2*)(Arow + lane * 2) = __floats2half2_rn(v.x, v.y);
        } else {
            *(uint2*)(Arow + lane * 4) =
                *(const uint2*)((const __half*)g_hh + (size_t)r * IN + lane * 4);
        }
    }
    if (warp == 1) {   /* s-values + zero-pad tail */
        if (lane < ET)
            Arow[5 * IN + lane] = __float2half_rn(g_ssum[((b * ET + lane) << 9) + n]);
        for (int k = 5 * IN + 4 + lane; k < KP; k += 32) Arow[k] = __half(0.f);
    }

    int e = warp;
    int lidx = ((b * ET + e) << 9) + n;
    int cnt = g_cnt[lidx];
    const unsigned short* nb = g_nbr + (size_t)lidx * MAXNBR;
    const __half* hb = h16 + (size_t)b * NN * IN + lane * VEC;

    float acc[VEC];
#pragma unroll
    for (int c = 0; c < VEC; c++) acc[c] = 0.f;

    int i = 0;
    for (; i + 4 <= cnt; i += 4) {
        uint2 q4 = *(const uint2*)(nb + i);
        int m0 = q4.x & 0xffff, m1 = q4.x >> 16;
        int m2 = q4.y & 0xffff, m3 = q4.y >> 16;
        if (VEC == 4) {
            uint2 f0 = *(const uint2*)(hb + (size_t)m0 * IN);
            uint2 f1 = *(const uint2*)(hb + (size_t)m1 * IN);
            uint2 f2 = *(const uint2*)(hb + (size_t)m2 * IN);
            uint2 f3 = *(const uint2*)(hb + (size_t)m3 * IN);
            float2 a, bb2;
            a = __half22float2(*(__half2*)&f0.x); bb2 = __half22float2(*(__half2*)&f0.y);
            acc[0] += a.x; acc[1] += a.y; acc[2] += bb2.x; acc[3] += bb2.y;
            a = __half22float2(*(__half2*)&f1.x); bb2 = __half22float2(*(__half2*)&f1.y);
            acc[0] += a.x; acc[1] += a.y; acc[2] += bb2.x; acc[3] += bb2.y;
            a = __half22float2(*(__half2*)&f2.x); bb2 = __half22float2(*(__half2*)&f2.y);
            acc[0] += a.x; acc[1] += a.y; acc[2] += bb2.x; acc[3] += bb2.y;
            a = __half22float2(*(__half2*)&f3.x); bb2 = __half22float2(*(__half2*)&f3.y);
            acc[0] += a.x; acc[1] += a.y; acc[2] += bb2.x; acc[3] += bb2.y;
        } else {
            unsigned f0 = *(const unsigned*)(hb + (size_t)m0 * IN);
            unsigned f1 = *(const unsigned*)(hb + (size_t)m1 * IN);
            unsigned f2 = *(const unsigned*)(hb + (size_t)m2 * IN);
            unsigned f3 = *(const unsigned*)(hb + (size_t)m3 * IN);
            float2 a;
            a = __half22float2(*(__half2*)&f0); acc[0] += a.x; acc[1] += a.y;
            a = __half22float2(*(__half2*)&f1); acc[0] += a.x; acc[1] += a.y;
            a = __half22float2(*(__half2*)&f2); acc[0] += a.x; acc[1] += a.y;
            a = __half22float2(*(__half2*)&f3); acc[0] += a.x; acc[1] += a.y;
        }
    }
    for (; i < cnt; i++) {
        int m = nb[i];
        if (VEC == 4) {
            uint2 f0 = *(const uint2*)(hb + (size_t)m * IN);
            float2 a = __half22float2(*(__half2*)&f0.x);
            float2 bb2 = __half22float2(*(__half2*)&f0.y);
            acc[0] += a.x; acc[1] += a.y; acc[2] += bb2.x; acc[3] += bb2.y;
        } else {
            unsigned f0 = *(const unsigned*)(hb + (size_t)m * IN);
            float2 a = __half22float2(*(__half2*)&f0);
            acc[0] += a.x; acc[1] += a.y;
        }
    }

    if (VEC == 4) {
        __half2 o0 = __floats2half2_rn(acc[0], acc[1]);
        __half2 o1 = __floats2half2_rn(acc[2], acc[3]);
        uint2 u; u.x = *(unsigned*)&o0; u.y = *(unsigned*)&o1;
        *(uint2*)(Arow + IN + e * IN + lane * 4) = u;
    } else {
        *(__half2*)(Arow + IN + e * IN + lane * 2) = __floats2half2_rn(acc[0], acc[1]);
    }
}

/* ------------- 7) FP16 tensor GEMM (m16n8k16) + fused BN stats --------- */
/* C(16384 x 128) = A(16384 x KP, fp16) @ Wt[*, wofs:wofs+KP]^T + bias      */
#define SROW 40   /* smem row pitch in halfs (32 data + 8 pad) */

__device__ __forceinline__ unsigned smaddr(const void* p) {
    return (unsigned)__cvta_generic_to_shared(p);
}
__device__ __forceinline__ void cpasync16(unsigned s, const void* g) {
    asm volatile("cp.async.cg.shared.global [%0], [%1], 16;\n" :: "r"(s), "l"(g));
}

__global__ void __launch_bounds__(256) k_gemm(int KP, const float* __restrict__ bias,
                                              int srcH, float* __restrict__ Cout,
                                              int wofs, int sb) {
    const __half* A = srcH ? (const __half*)g_hh : (const __half*)g_A;
    float* C = Cout ? Cout : (float*)g_pre;

    __shared__ __half sA[2][128 * SROW];
    __shared__ __half sB[2][128 * SROW];

    int tid = threadIdx.x;
    int lane = tid & 31, warp = tid >> 5;
    int wm = (warp >> 1) * 32, wn = (warp & 1) * 64;
    int grp = lane >> 2, qid = lane & 3;
    int rowbase = blockIdx.x * 128;
    int KB = KP >> 5;                   /* 32 halfs per k-tile */

    float acc[2][8][4];
#pragma unroll
    for (int a = 0; a < 2; a++)
#pragma unroll
        for (int bq = 0; bq < 8; bq++)
#pragma unroll
            for (int c = 0; c < 4; c++) acc[a][bq][c] = 0.f;

    auto issue = [&](int kb, int buf) {
        int kof = kb * 32;
#pragma unroll
        for (int i = 0; i < 2; i++) {
            int c = tid + i * 256, row = c >> 2, q = c & 3;
            cpasync16(smaddr(&sA[buf][row * SROW + q * 8]),
                      A + (size_t)(rowbase + row) * KP + kof + q * 8);
            cpasync16(smaddr(&sB[buf][row * SROW + q * 8]),
                      (const __half*)g_Wt + (size_t)row * WTCOLS + wofs + kof + q * 8);
        }
        asm volatile("cp.async.commit_group;\n" ::);
    };

    issue(0, 0);
    for (int kb = 0; kb < KB; kb++) {
        int buf = kb & 1;
        if (kb + 1 < KB) {
            issue(kb + 1, buf ^ 1);
            asm volatile("cp.async.wait_group 1;\n" ::);
        } else {
            asm volatile("cp.async.wait_group 0;\n" ::);
        }
        __syncthreads();

#pragma unroll
        for (int ks = 0; ks < 2; ks++) {
            int k0 = ks * 16;
            unsigned bf[8][2];
#pragma unroll
            for (int ni = 0; ni < 8; ni++) {
                const __half* bp = &sB[buf][(wn + ni * 8 + grp) * SROW + k0 + 2 * qid];
                bf[ni][0] = *(const unsigned*)bp;
                bf[ni][1] = *(const unsigned*)(bp + 8);
            }
#pragma unroll
            for (int mi = 0; mi < 2; mi++) {
                const __half* ap = &sA[buf][(wm + mi * 16 + grp) * SROW + k0 + 2 * qid];
                unsigned a0 = *(const unsigned*)ap;
                unsigned a1 = *(const unsigned*)(ap + 8 * SROW);
                unsigned a2 = *(const unsigned*)(ap + 8);
                unsigned a3 = *(const unsigned*)(ap + 8 * SROW + 8);
#pragma unroll
                for (int ni = 0; ni < 8; ni++) {
                    asm volatile(
                        "mma.sync.aligned.m16n8k16.row.col.f32.f16.f16.f32 "
                        "{%0,%1,%2,%3}, {%4,%5,%6,%7}, {%8,%9}, {%0,%1,%2,%3};\n"
                        : "+f"(acc[mi][ni][0]), "+f"(acc[mi][ni][1]),
                          "+f"(acc[mi][ni][2]), "+f"(acc[mi][ni][3])
                        : "r"(a0), "r"(a1), "r"(a2), "r"(a3),
                          "r"(bf[ni][0]), "r"(bf[ni][1]));
                }
            }
        }
        __syncthreads();
    }

    /* epilogue: +bias, store, per-row BN partial sums */
    float rs[2][2] = {{0.f,0.f},{0.f,0.f}};
    float rq[2][2] = {{0.f,0.f},{0.f,0.f}};
#pragma unroll
    for (int mi = 0; mi < 2; mi++) {
        int row = rowbase + wm + mi * 16 + grp;
#pragma unroll
        for (int ni = 0; ni < 8; ni++) {
            int col = wn + ni * 8 + qid * 2;
            float b0 = bias[col], b1 = bias[col + 1];
            float v0 = acc[mi][ni][0] + b0, v1 = acc[mi][ni][1] + b1;
            float v2 = acc[mi][ni][2] + b0, v3 = acc[mi][ni][3] + b1;
            C[(size_t)row * HID + col]           = v0;
            C[(size_t)row * HID + col + 1]       = v1;
            C[(size_t)(row + 8) * HID + col]     = v2;
            C[(size_t)(row + 8) * HID + col + 1] = v3;
            rs[mi][0] += v0 + v1; rq[mi][0] += v0 * v0 + v1 * v1;
            rs[mi][1] += v2 + v3; rq[mi][1] += v2 * v2 + v3 * v3;
        }
    }
    if (sb >= 0) {
#pragma unroll
        for (int mi = 0; mi < 2; mi++)
#pragma unroll
            for (int rr = 0; rr < 2; rr++) {
                rs[mi][rr] += __shfl_xor_sync(0xffffffffu, rs[mi][rr], 1);
                rs[mi][rr] += __shfl_xor_sync(0xffffffffu, rs[mi][rr], 2);
                rq[mi][rr] += __shfl_xor_sync(0xffffffffu, rq[mi][rr], 1);
                rq[mi][rr] += __shfl_xor_sync(0xffffffffu, rq[mi][rr], 2);
            }
        if (qid == 0) {
#pragma unroll
            for (int mi = 0; mi < 2; mi++)
#pragma unroll
                for (int rr = 0; rr < 2; rr++) {
                    int row = rowbase + wm + mi * 16 + grp + rr * 8;
                    int n = row & 511;
                    atomicAdd(&g_bnsum[sb * NN + n], rs[mi][rr]);
                    atomicAdd(&g_bnsq [sb * NN + n], rq[mi][rr]);
                }
        }
    }
}

/* ------------- 8) BN finalize + apply + ReLU (fp16 stages) ------------- */
template<bool H16>
__global__ void k_bnapply(const float* __restrict__ g, const float* __restrict__ bb,
                          int sb) {
    int i4 = blockIdx.x * 256 + threadIdx.x;     // over ROWS*HID/4
    float4 v = ((const float4*)g_pre)[i4];
    int r = i4 >> 5;
    int n = r & 511;
    const float invC = 1.f / (float)(MBATCH * HID);
    float mean = g_bnsum[sb * NN + n] * invC;
    float var  = g_bnsq [sb * NN + n] * invC - mean * mean;
    var = fmaxf(var, 0.f);
    float sc = g[n] * rsqrtf(var + EPSV);
    float sh = bb[n] - mean * sc;
    float x0 = fmaxf(v.x * sc + sh, 0.f);
    float x1 = fmaxf(v.y * sc + sh, 0.f);
    float x2 = fmaxf(v.z * sc + sh, 0.f);
    float x3 = fmaxf(v.w * sc + sh, 0.f);
    __half2 p0 = __floats2half2_rn(x0, x1);
    __half2 p1 = __floats2half2_rn(x2, x3);
    uint2 u; u.x = *(unsigned*)&p0; u.y = *(unsigned*)&p1;
    ((uint2*)g_hh)[i4] = u;
    if (H16) {
        float w = g_inv[r];
        __half2 h0 = __floats2half2_rn(w * x0, w * x1);
        __half2 h1 = __floats2half2_rn(w * x2, w * x3);
        uint2 u2; u2.x = *(unsigned*)&h0; u2.y = *(unsigned*)&h1;
        ((uint2*)g_h16)[i4] = u2;
    }
}

/* ---------------- driver ------------------------------------------------ */
extern "C" void kernel_launch(void* const* d_in, const int* in_sizes, int n_in,
                              void* d_out, int out_size) {
    const float* x   = (const float*)d_in[0];
    const float* adj = (const float*)d_in[1];
    const float* ws[3] = {(const float*)d_in[2],  (const float*)d_in[8],  (const float*)d_in[14]};
    const float* bs[3] = {(const float*)d_in[3],  (const float*)d_in[9],  (const float*)d_in[15]};
    const float* we[3] = {(const float*)d_in[4],  (const float*)d_in[10], (const float*)d_in[16]};
    const float* be[3] = {(const float*)d_in[5],  (const float*)d_in[11], (const float*)d_in[17]};
    const float* bg[3] = {(const float*)d_in[6],  (const float*)d_in[12], (const float*)d_in[18]};
    const float* bb[3] = {(const float*)d_in[7],  (const float*)d_in[13], (const float*)d_in[19]};
    const float* w1  = (const float*)d_in[20];
    const float* b1  = (const float*)d_in[21];
    const float* bfg = (const float*)d_in[22];
    const float* bfb = (const float*)d_in[23];
    const float* w2  = (const float*)d_in[24];
    const float* b2  = (const float*)d_in[25];

    (void)in_sizes; (void)n_in; (void)out_size;

    k_csr<<<(MBATCH * ET * NN) / 8, 256>>>(adj);
    k_deg<<<(MBATCH * NN) / 256, 256>>>();
    k_ssum<<<(MBATCH * ET * NN) / 256, 256>>>();
    k_stage0<<<(MBATCH * NN * IN0 / 4) / 256, 256>>>(x);
    k_wprep_all<<<(HID * WTCOLS + 255) / 256, 256>>>(
        ws[0], we[0], be[0], ws[1], we[1], be[1], ws[2], we[2], be[2], w1, w2);

    /* layer 0 */
    k_agg<IN0><<<ROWS, 128>>>(x, KP0);
    k_gemm<<<ROWS / 128, 256>>>(KP0, bs[0], 0, nullptr, WT0, 0);
    k_bnapply<true><<<ROWS * HID / 4 / 256, 256>>>(bg[0], bb[0], 0);

    /* layer 1 */
    k_agg<HID><<<ROWS, 128>>>((const float*)nullptr, KP12);
    k_gemm<<<ROWS / 128, 256>>>(KP12, bs[1], 0, nullptr, WT1, 1);
    k_bnapply<true><<<ROWS * HID / 4 / 256, 256>>>(bg[1], bb[1], 1);

    /* layer 2 */
    k_agg<HID><<<ROWS, 128>>>((const float*)nullptr, KP12);
    k_gemm<<<ROWS / 128, 256>>>(KP12, bs[2], 0, nullptr, WT2, 2);
    k_bnapply<true><<<ROWS * HID / 4 / 256, 256>>>(bg[2], bb[2], 2);

    /* final MLP */
    k_gemm<<<ROWS / 128, 256>>>(HID, b1, 1, nullptr, WT3, 3);
    k_bnapply<false><<<ROWS * HID / 4 / 256, 256>>>(bfg, bfb, 3);
    k_gemm<<<ROWS / 128, 256>>>(HID, b2, 1, (float*)d_out, WT4, -1);
}

// round 10
// speedup vs baseline: 3.5551x; 1.0123x over previous
#include <cuda_runtime.h>
#include <cuda_fp16.h>

#define MBATCH 32
#define ET 4
#define NN 512
#define IN0 64
#define HID 128
#define ROWS (MBATCH*NN)      /* 16384 */
#define MAXNBR 64
#define KP0 352               /* pad(5*64+4, 32)  */
#define KP12 672              /* pad(5*128+4, 32) */
#define EPSV 1e-5f

/* transposed-weight column offsets inside g_Wt[128][WTCOLS] */
#define WT0 0
#define WT1 352
#define WT2 1024
#define WT3 1696
#define WT4 1824
#define WTCOLS 1952

/* prep2 sub-grid block counts */
#define NB_SSUM   ((MBATCH*ET*NN)/256)            /* 256  */
#define NB_STAGE0 ((MBATCH*NN*IN0/4)/256)         /* 1024 */
#define NB_WPREP  ((HID*WTCOLS + 255)/256)        /* 976  */

/* ---------------- static device scratch (no allocation) ---------------- */
__device__ float          g_inv[MBATCH*NN];
__device__ float          g_ssum[MBATCH*ET*NN];
__device__ __align__(16) unsigned short g_nbr[MBATCH*ET*NN*MAXNBR];
__device__ int            g_cnt[MBATCH*ET*NN];              // clamped
__device__ int            g_cntfull[MBATCH*ET*NN];          // exact
__device__ __align__(16) __half g_A[ROWS*KP12];             // 22 MB
__device__ __align__(16) __half g_Wt[HID*WTCOLS];           // 0.5 MB
__device__ __align__(16) float  g_pre[ROWS*HID];            // 8.4 MB
__device__ __align__(16) __half g_hh[ROWS*HID];             // post-BN act, fp16
__device__ __align__(16) __half g_h16[ROWS*HID];            // inv-scaled act
__device__ __align__(16) __half g_x16[MBATCH*NN*IN0];       // inv-scaled x
__device__ float          g_bnsum[4*NN];
__device__ float          g_bnsq[4*NN];

/* ------------- 1) CSR build: one warp per (b,e,n) row, float4 reads ----- */
__global__ void k_csr(const float* __restrict__ adj) {
    int row  = blockIdx.x * 8 + (threadIdx.x >> 5);
    int lane = threadIdx.x & 31;
    int n    = row & (NN - 1);
    const float4* p = (const float4*)(adj + (size_t)row * NN);
    unsigned short* out = g_nbr + (size_t)row * MAXNBR;
    int cnt = 0;
    for (int it = 0; it < NN / 128; it++) {
        float4 v = p[it * 32 + lane];
        int mb = (it * 32 + lane) * 4;
        float vc[4] = {v.x, v.y, v.z, v.w};
#pragma unroll
        for (int c = 0; c < 4; c++) {
            bool pr = (vc[c] != 0.f) && (mb + c != n);
            unsigned msk = __ballot_sync(0xffffffffu, pr);
            if (pr) {
                int pos = cnt + __popc(msk & ((1u << lane) - 1u));
                if (pos < MAXNBR) out[pos] = (unsigned short)(mb + c);
            }
            cnt += __popc(msk);
        }
    }
    if (lane == 0) {
        g_cnt[row]     = cnt < MAXNBR ? cnt : MAXNBR;
        g_cntfull[row] = cnt;
    }
}

/* ------------- 2) inv degree from exact counts (adj symmetric, 0/1) ---- */
__global__ void k_deg() {
    int i = blockIdx.x * 256 + threadIdx.x;
    int b = i >> 9, m = i & 511;
    int d = 0;
#pragma unroll
    for (int e = 0; e < ET; e++) d += g_cntfull[((b * ET + e) << 9) + m];
    g_inv[i] = d > 0 ? 1.f / (float)d : 0.f;
}

/* ------------- 3) fused prep: ssum | stage0 | wprep (block dispatch) --- */
__global__ void k_prep2(const float* __restrict__ x,
    const float* __restrict__ ws0, const float* __restrict__ we0, const float* __restrict__ be0,
    const float* __restrict__ ws1, const float* __restrict__ we1, const float* __restrict__ be1,
    const float* __restrict__ ws2, const float* __restrict__ we2, const float* __restrict__ be2,
    const float* __restrict__ w1,  const float* __restrict__ w2) {
    int blk = blockIdx.x;
    if (blk < NB_SSUM) {
        /* per-row sum of inv over neighbors (layer-invariant) */
        int lidx = blk * 256 + threadIdx.x;
        int b = lidx >> 11;
        int cnt = g_cnt[lidx];
        const unsigned short* nb = g_nbr + (size_t)lidx * MAXNBR;
        const float* invb = g_inv + b * NN;
        float s = 0.f;
        for (int i = 0; i < cnt; i++) s += invb[nb[i]];
        g_ssum[lidx] = s;
        if (lidx < 4 * NN) { g_bnsum[lidx] = 0.f; g_bnsq[lidx] = 0.f; }
        return;
    }
    blk -= NB_SSUM;
    if (blk < NB_STAGE0) {
        /* stage inv-scaled x as fp16 */
        int i4 = blk * 256 + threadIdx.x;
        float4 v = ((const float4*)x)[i4];
        int r = i4 >> 4;
        float w = g_inv[r];
        __half2 h0 = __floats2half2_rn(w * v.x, w * v.y);
        __half2 h1 = __floats2half2_rn(w * v.z, w * v.w);
        uint2 u; u.x = *(unsigned*)&h0; u.y = *(unsigned*)&h1;
        ((uint2*)g_x16)[i4] = u;
        return;
    }
    blk -= NB_STAGE0;
    {
        /* transposed weight prep (fp16) */
        int idx = blk * 256 + threadIdx.x;
        if (idx >= HID * WTCOLS) return;
        int o = idx / WTCOLS, k = idx - o * WTCOLS;
        float v = 0.f;
        if (k < WT1) {                       /* layer0: IN=64 */
            int kk = k;
            if (kk < 64)       v = ws0[kk * HID + o];
            else if (kk < 320) { int e = (kk - 64) >> 6, j = (kk - 64) & 63;
                                 v = we0[j * (HID * ET) + o * ET + e]; }
            else if (kk < 324)   v = be0[o * ET + (kk - 320)];
        } else if (k < WT2) {                /* layer1 */
            int kk = k - WT1;
            if (kk < 128)      v = ws1[kk * HID + o];
            else if (kk < 640) { int e = (kk - 128) >> 7, j = (kk - 128) & 127;
                                 v = we1[j * (HID * ET) + o * ET + e]; }
            else if (kk < 644)   v = be1[o * ET + (kk - 640)];
        } else if (k < WT3) {                /* layer2 */
            int kk = k - WT2;
            if (kk < 128)      v = ws2[kk * HID + o];
            else if (kk < 640) { int e = (kk - 128) >> 7, j = (kk - 128) & 127;
                                 v = we2[j * (HID * ET) + o * ET + e]; }
            else if (kk < 644)   v = be2[o * ET + (kk - 640)];
        } else if (k < WT4) {
            v = w1[(k - WT3) * HID + o];
        } else {
            v = w2[(k - WT4) * HID + o];
        }
        g_Wt[o * WTCOLS + k] = __float2half_rn(v);
    }
}

/* ------------- 4) sparse aggregation: pipelined pure-sum gather -------- */
template<int IN>
__global__ void __launch_bounds__(128) k_agg(const float* __restrict__ x0, int KP) {
    constexpr int VEC = IN / 32;   // 4 for IN=128, 2 for IN=64
    const __half* __restrict__ h16 = (IN == IN0) ? (const __half*)g_x16
                                                 : (const __half*)g_h16;
    int r = blockIdx.x, b = r >> 9, n = r & 511;
    int warp = threadIdx.x >> 5, lane = threadIdx.x & 31;
    __half* Arow = g_A + (size_t)r * KP;

    if (warp == 0) {   /* self-feature copy */
        if (IN == IN0) {
            float2 v = *(const float2*)(x0 + (size_t)r * IN + lane * 2);
            *(__half2*)(Arow + lane * 2) = __floats2half2_rn(v.x, v.y);
        } else {
            *(uint2*)(Arow + lane * 4) =
                *(const uint2*)((const __half*)g_hh + (size_t)r * IN + lane * 4);
        }
    }
    if (warp == 1) {   /* s-values + zero-pad tail */
        if (lane < ET)
            Arow[5 * IN + lane] = __float2half_rn(g_ssum[((b * ET + lane) << 9) + n]);
        for (int k = 5 * IN + 4 + lane; k < KP; k += 32) Arow[k] = __half(0.f);
    }

    int e = warp;
    int lidx = ((b * ET + e) << 9) + n;
    int cnt = g_cnt[lidx];
    const unsigned short* nb = g_nbr + (size_t)lidx * MAXNBR;
    const uint2* nbq = (const uint2*)nb;      /* 16 groups of 4 u16 */
    const __half* hb = h16 + (size_t)b * NN * IN + lane * VEC;

    float acc[VEC];
#pragma unroll
    for (int c = 0; c < VEC; c++) acc[c] = 0.f;

    int i = 0;
    if (cnt >= 4) {
        uint2 qc = nbq[0];                    /* index prefetch, distance 1 */
#pragma unroll 2
        for (; i + 4 <= cnt; i += 4) {
            int g = (i >> 2) + 1;
            uint2 qn = nbq[g < 16 ? g : 15];  /* clamp: no OOB on last row */
            int m0 = qc.x & 0xffff, m1 = qc.x >> 16;
            int m2 = qc.y & 0xffff, m3 = qc.y >> 16;
            if (VEC == 4) {
                uint2 f0 = *(const uint2*)(hb + (size_t)m0 * IN);
                uint2 f1 = *(const uint2*)(hb + (size_t)m1 * IN);
                uint2 f2 = *(const uint2*)(hb + (size_t)m2 * IN);
                uint2 f3 = *(const uint2*)(hb + (size_t)m3 * IN);
                float2 a, bb2;
                a = __half22float2(*(__half2*)&f0.x); bb2 = __half22float2(*(__half2*)&f0.y);
                acc[0] += a.x; acc[1] += a.y; acc[2] += bb2.x; acc[3] += bb2.y;
                a = __half22float2(*(__half2*)&f1.x); bb2 = __half22float2(*(__half2*)&f1.y);
                acc[0] += a.x; acc[1] += a.y; acc[2] += bb2.x; acc[3] += bb2.y;
                a = __half22float2(*(__half2*)&f2.x); bb2 = __half22float2(*(__half2*)&f2.y);
                acc[0] += a.x; acc[1] += a.y; acc[2] += bb2.x; acc[3] += bb2.y;
                a = __half22float2(*(__half2*)&f3.x); bb2 = __half22float2(*(__half2*)&f3.y);
                acc[0] += a.x; acc[1] += a.y; acc[2] += bb2.x; acc[3] += bb2.y;
            } else {
                unsigned f0 = *(const unsigned*)(hb + (size_t)m0 * IN);
                unsigned f1 = *(const unsigned*)(hb + (size_t)m1 * IN);
                unsigned f2 = *(const unsigned*)(hb + (size_t)m2 * IN);
                unsigned f3 = *(const unsigned*)(hb + (size_t)m3 * IN);
                float2 a;
                a = __half22float2(*(__half2*)&f0); acc[0] += a.x; acc[1] += a.y;
                a = __half22float2(*(__half2*)&f1); acc[0] += a.x; acc[1] += a.y;
                a = __half22float2(*(__half2*)&f2); acc[0] += a.x; acc[1] += a.y;
                a = __half22float2(*(__half2*)&f3); acc[0] += a.x; acc[1] += a.y;
            }
            qc = qn;
        }
    }
    for (; i < cnt; i++) {
        int m = nb[i];
        if (VEC == 4) {
            uint2 f0 = *(const uint2*)(hb + (size_t)m * IN);
            float2 a = __half22float2(*(__half2*)&f0.x);
            float2 bb2 = __half22float2(*(__half2*)&f0.y);
            acc[0] += a.x; acc[1] += a.y; acc[2] += bb2.x; acc[3] += bb2.y;
        } else {
            unsigned f0 = *(const unsigned*)(hb + (size_t)m * IN);
            float2 a = __half22float2(*(__half2*)&f0);
            acc[0] += a.x; acc[1] += a.y;
        }
    }

    if (VEC == 4) {
        __half2 o0 = __floats2half2_rn(acc[0], acc[1]);
        __half2 o1 = __floats2half2_rn(acc[2], acc[3]);
        uint2 u; u.x = *(unsigned*)&o0; u.y = *(unsigned*)&o1;
        *(uint2*)(Arow + IN + e * IN + lane * 4) = u;
    } else {
        *(__half2*)(Arow + IN + e * IN + lane * 2) = __floats2half2_rn(acc[0], acc[1]);
    }
}

/* ------------- 5) FP16 tensor GEMM (m16n8k16) + fused BN stats --------- */
#define SROW 40   /* smem row pitch in halfs (32 data + 8 pad) */

__device__ __forceinline__ unsigned smaddr(const void* p) {
    return (unsigned)__cvta_generic_to_shared(p);
}
__device__ __forceinline__ void cpasync16(unsigned s, const void* g) {
    asm volatile("cp.async.cg.shared.global [%0], [%1], 16;\n" :: "r"(s), "l"(g));
}

__global__ void __launch_bounds__(256) k_gemm(int KP, const float* __restrict__ bias,
                                              int srcH, float* __restrict__ Cout,
                                              int wofs, int sb) {
    const __half* A = srcH ? (const __half*)g_hh : (const __half*)g_A;
    float* C = Cout ? Cout : (float*)g_pre;

    __shared__ __half sA[2][128 * SROW];
    __shared__ __half sB[2][128 * SROW];

    int tid = threadIdx.x;
    int lane = tid & 31, warp = tid >> 5;
    int wm = (warp >> 1) * 32, wn = (warp & 1) * 64;
    int grp = lane >> 2, qid = lane & 3;
    int rowbase = blockIdx.x * 128;
    int KB = KP >> 5;

    float acc[2][8][4];
#pragma unroll
    for (int a = 0; a < 2; a++)
#pragma unroll
        for (int bq = 0; bq < 8; bq++)
#pragma unroll
            for (int c = 0; c < 4; c++) acc[a][bq][c] = 0.f;

    auto issue = [&](int kb, int buf) {
        int kof = kb * 32;
#pragma unroll
        for (int i = 0; i < 2; i++) {
            int c = tid + i * 256, row = c >> 2, q = c & 3;
            cpasync16(smaddr(&sA[buf][row * SROW + q * 8]),
                      A + (size_t)(rowbase + row) * KP + kof + q * 8);
            cpasync16(smaddr(&sB[buf][row * SROW + q * 8]),
                      (const __half*)g_Wt + (size_t)row * WTCOLS + wofs + kof + q * 8);
        }
        asm volatile("cp.async.commit_group;\n" ::);
    };

    issue(0, 0);
    for (int kb = 0; kb < KB; kb++) {
        int buf = kb & 1;
        if (kb + 1 < KB) {
            issue(kb + 1, buf ^ 1);
            asm volatile("cp.async.wait_group 1;\n" ::);
        } else {
            asm volatile("cp.async.wait_group 0;\n" ::);
        }
        __syncthreads();

#pragma unroll
        for (int ks = 0; ks < 2; ks++) {
            int k0 = ks * 16;
            unsigned bf[8][2];
#pragma unroll
            for (int ni = 0; ni < 8; ni++) {
                const __half* bp = &sB[buf][(wn + ni * 8 + grp) * SROW + k0 + 2 * qid];
                bf[ni][0] = *(const unsigned*)bp;
                bf[ni][1] = *(const unsigned*)(bp + 8);
            }
#pragma unroll
            for (int mi = 0; mi < 2; mi++) {
                const __half* ap = &sA[buf][(wm + mi * 16 + grp) * SROW + k0 + 2 * qid];
                unsigned a0 = *(const unsigned*)ap;
                unsigned a1 = *(const unsigned*)(ap + 8 * SROW);
                unsigned a2 = *(const unsigned*)(ap + 8);
                unsigned a3 = *(const unsigned*)(ap + 8 * SROW + 8);
#pragma unroll
                for (int ni = 0; ni < 8; ni++) {
                    asm volatile(
                        "mma.sync.aligned.m16n8k16.row.col.f32.f16.f16.f32 "
                        "{%0,%1,%2,%3}, {%4,%5,%6,%7}, {%8,%9}, {%0,%1,%2,%3};\n"
                        : "+f"(acc[mi][ni][0]), "+f"(acc[mi][ni][1]),
                          "+f"(acc[mi][ni][2]), "+f"(acc[mi][ni][3])
                        : "r"(a0), "r"(a1), "r"(a2), "r"(a3),
                          "r"(bf[ni][0]), "r"(bf[ni][1]));
                }
            }
        }
        __syncthreads();
    }

    /* epilogue: +bias, store, per-row BN partial sums */
    float rs[2][2] = {{0.f,0.f},{0.f,0.f}};
    float rq[2][2] = {{0.f,0.f},{0.f,0.f}};
#pragma unroll
    for (int mi = 0; mi < 2; mi++) {
        int row = rowbase + wm + mi * 16 + grp;
#pragma unroll
        for (int ni = 0; ni < 8; ni++) {
            int col = wn + ni * 8 + qid * 2;
            float b0 = bias[col], b1 = bias[col + 1];
            float v0 = acc[mi][ni][0] + b0, v1 = acc[mi][ni][1] + b1;
            float v2 = acc[mi][ni][2] + b0, v3 = acc[mi][ni][3] + b1;
            C[(size_t)row * HID + col]           = v0;
            C[(size_t)row * HID + col + 1]       = v1;
            C[(size_t)(row + 8) * HID + col]     = v2;
            C[(size_t)(row + 8) * HID + col + 1] = v3;
            rs[mi][0] += v0 + v1; rq[mi][0] += v0 * v0 + v1 * v1;
            rs[mi][1] += v2 + v3; rq[mi][1] += v2 * v2 + v3 * v3;
        }
    }
    if (sb >= 0) {
#pragma unroll
        for (int mi = 0; mi < 2; mi++)
#pragma unroll
            for (int rr = 0; rr < 2; rr++) {
                rs[mi][rr] += __shfl_xor_sync(0xffffffffu, rs[mi][rr], 1);
                rs[mi][rr] += __shfl_xor_sync(0xffffffffu, rs[mi][rr], 2);
                rq[mi][rr] += __shfl_xor_sync(0xffffffffu, rq[mi][rr], 1);
                rq[mi][rr] += __shfl_xor_sync(0xffffffffu, rq[mi][rr], 2);
            }
        if (qid == 0) {
#pragma unroll
            for (int mi = 0; mi < 2; mi++)
#pragma unroll
                for (int rr = 0; rr < 2; rr++) {
                    int row = rowbase + wm + mi * 16 + grp + rr * 8;
                    int n = row & 511;
                    atomicAdd(&g_bnsum[sb * NN + n], rs[mi][rr]);
                    atomicAdd(&g_bnsq [sb * NN + n], rq[mi][rr]);
                }
        }
    }
}

/* ------------- 6) BN finalize + apply + ReLU (fp16 stages) ------------- */
template<bool H16>
__global__ void k_bnapply(const float* __restrict__ g, const float* __restrict__ bb,
                          int sb) {
    int i4 = blockIdx.x * 256 + threadIdx.x;
    float4 v = ((const float4*)g_pre)[i4];
    int r = i4 >> 5;
    int n = r & 511;
    const float invC = 1.f / (float)(MBATCH * HID);
    float mean = g_bnsum[sb * NN + n] * invC;
    float var  = g_bnsq [sb * NN + n] * invC - mean * mean;
    var = fmaxf(var, 0.f);
    float sc = g[n] * rsqrtf(var + EPSV);
    float sh = bb[n] - mean * sc;
    float x0 = fmaxf(v.x * sc + sh, 0.f);
    float x1 = fmaxf(v.y * sc + sh, 0.f);
    float x2 = fmaxf(v.z * sc + sh, 0.f);
    float x3 = fmaxf(v.w * sc + sh, 0.f);
    __half2 p0 = __floats2half2_rn(x0, x1);
    __half2 p1 = __floats2half2_rn(x2, x3);
    uint2 u; u.x = *(unsigned*)&p0; u.y = *(unsigned*)&p1;
    ((uint2*)g_hh)[i4] = u;
    if (H16) {
        float w = g_inv[r];
        __half2 h0 = __floats2half2_rn(w * x0, w * x1);
        __half2 h1 = __floats2half2_rn(w * x2, w * x3);
        uint2 u2; u2.x = *(unsigned*)&h0; u2.y = *(unsigned*)&h1;
        ((uint2*)g_h16)[i4] = u2;
    }
}

/* ---------------- driver ------------------------------------------------ */
extern "C" void kernel_launch(void* const* d_in, const int* in_sizes, int n_in,
                              void* d_out, int out_size) {
    const float* x   = (const float*)d_in[0];
    const float* adj = (const float*)d_in[1];
    const float* ws[3] = {(const float*)d_in[2],  (const float*)d_in[8],  (const float*)d_in[14]};
    const float* bs[3] = {(const float*)d_in[3],  (const float*)d_in[9],  (const float*)d_in[15]};
    const float* we[3] = {(const float*)d_in[4],  (const float*)d_in[10], (const float*)d_in[16]};
    const float* be[3] = {(const float*)d_in[5],  (const float*)d_in[11], (const float*)d_in[17]};
    const float* bg[3] = {(const float*)d_in[6],  (const float*)d_in[12], (const float*)d_in[18]};
    const float* bb[3] = {(const float*)d_in[7],  (const float*)d_in[13], (const float*)d_in[19]};
    const float* w1  = (const float*)d_in[20];
    const float* b1  = (const float*)d_in[21];
    const float* bfg = (const float*)d_in[22];
    const float* bfb = (const float*)d_in[23];
    const float* w2  = (const float*)d_in[24];
    const float* b2  = (const float*)d_in[25];

    (void)in_sizes; (void)n_in; (void)out_size;

    k_csr<<<(MBATCH * ET * NN) / 8, 256>>>(adj);
    k_deg<<<(MBATCH * NN) / 256, 256>>>();
    k_prep2<<<NB_SSUM + NB_STAGE0 + NB_WPREP, 256>>>(
        x, ws[0], we[0], be[0], ws[1], we[1], be[1], ws[2], we[2], be[2], w1, w2);

    /* layer 0 */
    k_agg<IN0><<<ROWS, 128>>>(x, KP0);
    k_gemm<<<ROWS / 128, 256>>>(KP0, bs[0], 0, nullptr, WT0, 0);
    k_bnapply<true><<<ROWS * HID / 4 / 256, 256>>>(bg[0], bb[0], 0);

    /* layer 1 */
    k_agg<HID><<<ROWS, 128>>>((const float*)nullptr, KP12);
    k_gemm<<<ROWS / 128, 256>>>(KP12, bs[1], 0, nullptr, WT1, 1);
    k_bnapply<true><<<ROWS * HID / 4 / 256, 256>>>(bg[1], bb[1], 1);

    /* layer 2 */
    k_agg<HID><<<ROWS, 128>>>((const float*)nullptr, KP12);
    k_gemm<<<ROWS / 128, 256>>>(KP12, bs[2], 0, nullptr, WT2, 2);
    k_bnapply<true><<<ROWS * HID / 4 / 256, 256>>>(bg[2], bb[2], 2);

    /* final MLP */
    k_gemm<<<ROWS / 128, 256>>>(HID, b1, 1, nullptr, WT3, 3);
    k_bnapply<false><<<ROWS * HID / 4 / 256, 256>>>(bfg, bfb, 3);
    k_gemm<<<ROWS / 128, 256>>>(HID, b2, 1, (float*)d_out, WT4, -1);
}

// round 11
// speedup vs baseline: 3.6579x; 1.0289x over previous
#include <cuda_runtime.h>
#include <cuda_fp16.h>

#define MBATCH 32
#define ET 4
#define NN 512
#define IN0 64
#define HID 128
#define ROWS (MBATCH*NN)      /* 16384 */
#define MAXNBR 64
#define KP0 352               /* pad(5*64+4, 32)  */
#define KP12 672              /* pad(5*128+4, 32) */
#define EPSV 1e-5f

/* transposed-weight column offsets inside g_Wt[128][WTCOLS] */
#define WT0 0
#define WT1 352
#define WT2 1024
#define WT3 1696
#define WT4 1824
#define WTCOLS 1952

/* prep2 sub-grid block counts */
#define NB_SSUM   ((MBATCH*ET*NN)/256)            /* 256  */
#define NB_STAGE0 ((MBATCH*NN*IN0/4)/256)         /* 1024 */
#define NB_WPREP  ((HID*WTCOLS + 255)/256)        /* 976  */

/* ---------------- static device scratch (no allocation) ---------------- */
__device__ float          g_inv[MBATCH*NN];
__device__ float          g_ssum[MBATCH*ET*NN];
__device__ __align__(16) unsigned g_nbrO[MBATCH*ET*NN*MAXNBR];   /* m*64 (half units) */
__device__ int            g_cnt[MBATCH*ET*NN];              // clamped
__device__ int            g_cntfull[MBATCH*ET*NN];          // exact
__device__ __align__(16) __half g_A[ROWS*KP12];             // 22 MB
__device__ __align__(16) __half g_Wt[HID*WTCOLS];           // 0.5 MB
__device__ __align__(16) float  g_pre[ROWS*HID];            // 8.4 MB
__device__ __align__(16) __half g_hh[ROWS*HID];             // post-BN act, fp16
__device__ __align__(16) __half g_h16[ROWS*HID];            // inv-scaled act
__device__ __align__(16) __half g_x16[MBATCH*NN*IN0];       // inv-scaled x
__device__ float          g_bnsum[4*NN];
__device__ float          g_bnsq[4*NN];

/* ------------- 1) CSR build: one warp per (b,e,n) row, float4 reads ----- */
__global__ void k_csr(const float* __restrict__ adj) {
    int row  = blockIdx.x * 8 + (threadIdx.x >> 5);
    int lane = threadIdx.x & 31;
    int n    = row & (NN - 1);
    const float4* p = (const float4*)(adj + (size_t)row * NN);
    unsigned* out = g_nbrO + (size_t)row * MAXNBR;
    int cnt = 0;
    for (int it = 0; it < NN / 128; it++) {
        float4 v = p[it * 32 + lane];
        int mb = (it * 32 + lane) * 4;
        float vc[4] = {v.x, v.y, v.z, v.w};
#pragma unroll
        for (int c = 0; c < 4; c++) {
            bool pr = (vc[c] != 0.f) && (mb + c != n);
            unsigned msk = __ballot_sync(0xffffffffu, pr);
            if (pr) {
                int pos = cnt + __popc(msk & ((1u << lane) - 1u));
                if (pos < MAXNBR) out[pos] = (unsigned)(mb + c) << 6;
            }
            cnt += __popc(msk);
        }
    }
    if (lane == 0) {
        g_cnt[row]     = cnt < MAXNBR ? cnt : MAXNBR;
        g_cntfull[row] = cnt;
    }
}

/* ------------- 2) inv degree from exact counts (adj symmetric, 0/1) ---- */
__global__ void k_deg() {
    int i = blockIdx.x * 256 + threadIdx.x;
    int b = i >> 9, m = i & 511;
    int d = 0;
#pragma unroll
    for (int e = 0; e < ET; e++) d += g_cntfull[((b * ET + e) << 9) + m];
    g_inv[i] = d > 0 ? 1.f / (float)d : 0.f;
}

/* ------------- 3) fused prep: ssum | stage0 | wprep (block dispatch) --- */
__global__ void k_prep2(const float* __restrict__ x,
    const float* __restrict__ ws0, const float* __restrict__ we0, const float* __restrict__ be0,
    const float* __restrict__ ws1, const float* __restrict__ we1, const float* __restrict__ be1,
    const float* __restrict__ ws2, const float* __restrict__ we2, const float* __restrict__ be2,
    const float* __restrict__ w1,  const float* __restrict__ w2) {
    int blk = blockIdx.x;
    if (blk < NB_SSUM) {
        int lidx = blk * 256 + threadIdx.x;
        int b = lidx >> 11;
        int cnt = g_cnt[lidx];
        const unsigned* nb = g_nbrO + (size_t)lidx * MAXNBR;
        const float* invb = g_inv + b * NN;
        float s = 0.f;
        for (int i = 0; i < cnt; i++) s += invb[nb[i] >> 6];
        g_ssum[lidx] = s;
        if (lidx < 4 * NN) { g_bnsum[lidx] = 0.f; g_bnsq[lidx] = 0.f; }
        return;
    }
    blk -= NB_SSUM;
    if (blk < NB_STAGE0) {
        int i4 = blk * 256 + threadIdx.x;
        float4 v = ((const float4*)x)[i4];
        int r = i4 >> 4;
        float w = g_inv[r];
        __half2 h0 = __floats2half2_rn(w * v.x, w * v.y);
        __half2 h1 = __floats2half2_rn(w * v.z, w * v.w);
        uint2 u; u.x = *(unsigned*)&h0; u.y = *(unsigned*)&h1;
        ((uint2*)g_x16)[i4] = u;
        return;
    }
    blk -= NB_STAGE0;
    {
        int idx = blk * 256 + threadIdx.x;
        if (idx >= HID * WTCOLS) return;
        int o = idx / WTCOLS, k = idx - o * WTCOLS;
        float v = 0.f;
        if (k < WT1) {
            int kk = k;
            if (kk < 64)       v = ws0[kk * HID + o];
            else if (kk < 320) { int e = (kk - 64) >> 6, j = (kk - 64) & 63;
                                 v = we0[j * (HID * ET) + o * ET + e]; }
            else if (kk < 324)   v = be0[o * ET + (kk - 320)];
        } else if (k < WT2) {
            int kk = k - WT1;
            if (kk < 128)      v = ws1[kk * HID + o];
            else if (kk < 640) { int e = (kk - 128) >> 7, j = (kk - 128) & 127;
                                 v = we1[j * (HID * ET) + o * ET + e]; }
            else if (kk < 644)   v = be1[o * ET + (kk - 640)];
        } else if (k < WT3) {
            int kk = k - WT2;
            if (kk < 128)      v = ws2[kk * HID + o];
            else if (kk < 640) { int e = (kk - 128) >> 7, j = (kk - 128) & 127;
                                 v = we2[j * (HID * ET) + o * ET + e]; }
            else if (kk < 644)   v = be2[o * ET + (kk - 640)];
        } else if (k < WT4) {
            v = w1[(k - WT3) * HID + o];
        } else {
            v = w2[(k - WT4) * HID + o];
        }
        g_Wt[o * WTCOLS + k] = __float2half_rn(v);
    }
}

/* ------------- 4) sparse aggregation: fp16 tree-sum gather ------------- */
template<int IN>
__global__ void __launch_bounds__(128) k_agg(const float* __restrict__ x0, int KP) {
    constexpr int VEC = IN / 32;   // 4 for IN=128, 2 for IN=64
    constexpr int STRIDE = IN / 64;  // off units -> half units multiplier
    const __half* __restrict__ h16 = (IN == IN0) ? (const __half*)g_x16
                                                 : (const __half*)g_h16;
    int r = blockIdx.x, b = r >> 9, n = r & 511;
    int warp = threadIdx.x >> 5, lane = threadIdx.x & 31;
    __half* Arow = g_A + (size_t)r * KP;

    if (warp == 0) {   /* self-feature copy */
        if (IN == IN0) {
            float2 v = *(const float2*)(x0 + (size_t)r * IN + lane * 2);
            *(__half2*)(Arow + lane * 2) = __floats2half2_rn(v.x, v.y);
        } else {
            *(uint2*)(Arow + lane * 4) =
                *(const uint2*)((const __half*)g_hh + (size_t)r * IN + lane * 4);
        }
    }
    if (warp == 1) {   /* s-values + zero-pad tail */
        if (lane < ET)
            Arow[5 * IN + lane] = __float2half_rn(g_ssum[((b * ET + lane) << 9) + n]);
        for (int k = 5 * IN + 4 + lane; k < KP; k += 32) Arow[k] = __half(0.f);
    }

    int e = warp;
    int lidx = ((b * ET + e) << 9) + n;
    int cnt = g_cnt[lidx];
    const unsigned* nb = g_nbrO + (size_t)lidx * MAXNBR;
    const uint4* nbq = (const uint4*)nb;      /* 16 groups of 4 u32 offsets */
    const __half* hb = h16 + (size_t)b * NN * IN + lane * VEC;

    float acc[VEC];
#pragma unroll
    for (int c = 0; c < VEC; c++) acc[c] = 0.f;

    int i = 0;
    if (cnt >= 4) {
        uint4 qc = nbq[0];                    /* offset prefetch, distance 1 */
        for (; i + 4 <= cnt; i += 4) {
            int g = (i >> 2) + 1;
            uint4 qn = nbq[g < 16 ? g : 15];
            const __half* p0 = hb + (size_t)qc.x * STRIDE;
            const __half* p1 = hb + (size_t)qc.y * STRIDE;
            const __half* p2 = hb + (size_t)qc.z * STRIDE;
            const __half* p3 = hb + (size_t)qc.w * STRIDE;
            if (VEC == 4) {
                uint2 f0 = *(const uint2*)p0;
                uint2 f1 = *(const uint2*)p1;
                uint2 f2 = *(const uint2*)p2;
                uint2 f3 = *(const uint2*)p3;
                /* fp16 depth-2 tree per half2 column, one convert per batch */
                __half2 sx = __hadd2(__hadd2(*(__half2*)&f0.x, *(__half2*)&f1.x),
                                     __hadd2(*(__half2*)&f2.x, *(__half2*)&f3.x));
                __half2 sy = __hadd2(__hadd2(*(__half2*)&f0.y, *(__half2*)&f1.y),
                                     __hadd2(*(__half2*)&f2.y, *(__half2*)&f3.y));
                float2 a = __half22float2(sx);
                float2 bb2 = __half22float2(sy);
                acc[0] += a.x; acc[1] += a.y; acc[2] += bb2.x; acc[3] += bb2.y;
            } else {
                unsigned f0 = *(const unsigned*)p0;
                unsigned f1 = *(const unsigned*)p1;
                unsigned f2 = *(const unsigned*)p2;
                unsigned f3 = *(const unsigned*)p3;
                __half2 s = __hadd2(__hadd2(*(__half2*)&f0, *(__half2*)&f1),
                                    __hadd2(*(__half2*)&f2, *(__half2*)&f3));
                float2 a = __half22float2(s);
                acc[0] += a.x; acc[1] += a.y;
            }
            qc = qn;
        }
    }
    for (; i < cnt; i++) {
        const __half* p = hb + (size_t)nb[i] * STRIDE;
        if (VEC == 4) {
            uint2 f0 = *(const uint2*)p;
            float2 a = __half22float2(*(__half2*)&f0.x);
            float2 bb2 = __half22float2(*(__half2*)&f0.y);
            acc[0] += a.x; acc[1] += a.y; acc[2] += bb2.x; acc[3] += bb2.y;
        } else {
            unsigned f0 = *(const unsigned*)p;
            float2 a = __half22float2(*(__half2*)&f0);
            acc[0] += a.x; acc[1] += a.y;
        }
    }

    if (VEC == 4) {
        __half2 o0 = __floats2half2_rn(acc[0], acc[1]);
        __half2 o1 = __floats2half2_rn(acc[2], acc[3]);
        uint2 u; u.x = *(unsigned*)&o0; u.y = *(unsigned*)&o1;
        *(uint2*)(Arow + IN + e * IN + lane * 4) = u;
    } else {
        *(__half2*)(Arow + IN + e * IN + lane * 2) = __floats2half2_rn(acc[0], acc[1]);
    }
}

/* ------------- 5) FP16 tensor GEMM (m16n8k16, ldmatrix) + BN stats ----- */
#define SROW 40   /* smem row pitch in halfs (32 data + 8 pad) */

__device__ __forceinline__ unsigned smaddr(const void* p) {
    return (unsigned)__cvta_generic_to_shared(p);
}
__device__ __forceinline__ void cpasync16(unsigned s, const void* g) {
    asm volatile("cp.async.cg.shared.global [%0], [%1], 16;\n" :: "r"(s), "l"(g));
}
__device__ __forceinline__ void ldsm4(unsigned& r0, unsigned& r1, unsigned& r2,
                                      unsigned& r3, unsigned addr) {
    asm volatile("ldmatrix.sync.aligned.m8n8.x4.shared.b16 {%0,%1,%2,%3}, [%4];\n"
                 : "=r"(r0), "=r"(r1), "=r"(r2), "=r"(r3) : "r"(addr));
}

__global__ void __launch_bounds__(256) k_gemm(int KP, const float* __restrict__ bias,
                                              int srcH, float* __restrict__ Cout,
                                              int wofs, int sb) {
    const __half* A = srcH ? (const __half*)g_hh : (const __half*)g_A;
    float* C = Cout ? Cout : (float*)g_pre;

    __shared__ __half sA[2][128 * SROW];
    __shared__ __half sB[2][128 * SROW];
    const unsigned BUFB = 128 * SROW * 2;        /* bytes per buffer */

    int tid = threadIdx.x;
    int lane = tid & 31, warp = tid >> 5;
    int wm = (warp >> 1) * 32, wn = (warp & 1) * 64;
    int grp = lane >> 2, qid = lane & 3;
    int rowbase = blockIdx.x * 128;
    int KB = KP >> 5;

    /* ldmatrix per-lane addresses (bytes, relative to buffer base) */
    unsigned aBase = smaddr(&sA[0][0]);
    unsigned bBase = smaddr(&sB[0][0]);
    int l7 = lane & 7, lb3 = (lane >> 3) & 1, lb4 = lane >> 4;
    unsigned aOff[2], bOff[4];
#pragma unroll
    for (int mi = 0; mi < 2; mi++)
        aOff[mi] = ((wm + mi * 16 + lb3 * 8 + l7) * SROW + lb4 * 8) * 2;
#pragma unroll
    for (int p = 0; p < 4; p++)
        bOff[p] = ((wn + p * 16 + lb4 * 8 + l7) * SROW + lb3 * 8) * 2;

    float acc[2][8][4];
#pragma unroll
    for (int a = 0; a < 2; a++)
#pragma unroll
        for (int bq = 0; bq < 8; bq++)
#pragma unroll
            for (int c = 0; c < 4; c++) acc[a][bq][c] = 0.f;

    auto issue = [&](int kb, int buf) {
        int kof = kb * 32;
#pragma unroll
        for (int i = 0; i < 2; i++) {
            int c = tid + i * 256, row = c >> 2, q = c & 3;
            cpasync16(smaddr(&sA[buf][row * SROW + q * 8]),
                      A + (size_t)(rowbase + row) * KP + kof + q * 8);
            cpasync16(smaddr(&sB[buf][row * SROW + q * 8]),
                      (const __half*)g_Wt + (size_t)row * WTCOLS + wofs + kof + q * 8);
        }
        asm volatile("cp.async.commit_group;\n" ::);
    };

    issue(0, 0);
    for (int kb = 0; kb < KB; kb++) {
        int buf = kb & 1;
        if (kb + 1 < KB) {
            issue(kb + 1, buf ^ 1);
            asm volatile("cp.async.wait_group 1;\n" ::);
        } else {
            asm volatile("cp.async.wait_group 0;\n" ::);
        }
        __syncthreads();

#pragma unroll
        for (int ks = 0; ks < 2; ks++) {
            unsigned kby = ks * 32 + buf * BUFB;
            unsigned bf[8][2];
#pragma unroll
            for (int p = 0; p < 4; p++)
                ldsm4(bf[2*p][0], bf[2*p][1], bf[2*p+1][0], bf[2*p+1][1],
                      bBase + bOff[p] + kby);
#pragma unroll
            for (int mi = 0; mi < 2; mi++) {
                unsigned a0, a1, a2, a3;
                ldsm4(a0, a1, a2, a3, aBase + aOff[mi] + kby);
#pragma unroll
                for (int ni = 0; ni < 8; ni++) {
                    asm volatile(
                        "mma.sync.aligned.m16n8k16.row.col.f32.f16.f16.f32 "
                        "{%0,%1,%2,%3}, {%4,%5,%6,%7}, {%8,%9}, {%0,%1,%2,%3};\n"
                        : "+f"(acc[mi][ni][0]), "+f"(acc[mi][ni][1]),
                          "+f"(acc[mi][ni][2]), "+f"(acc[mi][ni][3])
                        : "r"(a0), "r"(a1), "r"(a2), "r"(a3),
                          "r"(bf[ni][0]), "r"(bf[ni][1]));
                }
            }
        }
        __syncthreads();
    }

    /* epilogue: +bias, store, per-row BN partial sums */
    float rs[2][2] = {{0.f,0.f},{0.f,0.f}};
    float rq[2][2] = {{0.f,0.f},{0.f,0.f}};
#pragma unroll
    for (int mi = 0; mi < 2; mi++) {
        int row = rowbase + wm + mi * 16 + grp;
#pragma unroll
        for (int ni = 0; ni < 8; ni++) {
            int col = wn + ni * 8 + qid * 2;
            float b0 = bias[col], b1 = bias[col + 1];
            float v0 = acc[mi][ni][0] + b0, v1 = acc[mi][ni][1] + b1;
            float v2 = acc[mi][ni][2] + b0, v3 = acc[mi][ni][3] + b1;
            C[(size_t)row * HID + col]           = v0;
            C[(size_t)row * HID + col + 1]       = v1;
            C[(size_t)(row + 8) * HID + col]     = v2;
            C[(size_t)(row + 8) * HID + col + 1] = v3;
            rs[mi][0] += v0 + v1; rq[mi][0] += v0 * v0 + v1 * v1;
            rs[mi][1] += v2 + v3; rq[mi][1] += v2 * v2 + v3 * v3;
        }
    }
    if (sb >= 0) {
#pragma unroll
        for (int mi = 0; mi < 2; mi++)
#pragma unroll
            for (int rr = 0; rr < 2; rr++) {
                rs[mi][rr] += __shfl_xor_sync(0xffffffffu, rs[mi][rr], 1);
                rs[mi][rr] += __shfl_xor_sync(0xffffffffu, rs[mi][rr], 2);
                rq[mi][rr] += __shfl_xor_sync(0xffffffffu, rq[mi][rr], 1);
                rq[mi][rr] += __shfl_xor_sync(0xffffffffu, rq[mi][rr], 2);
            }
        if (qid == 0) {
#pragma unroll
            for (int mi = 0; mi < 2; mi++)
#pragma unroll
                for (int rr = 0; rr < 2; rr++) {
                    int row = rowbase + wm + mi * 16 + grp + rr * 8;
                    int n = row & 511;
                    atomicAdd(&g_bnsum[sb * NN + n], rs[mi][rr]);
                    atomicAdd(&g_bnsq [sb * NN + n], rq[mi][rr]);
                }
        }
    }
}

/* ------------- 6) BN finalize + apply + ReLU (fp16 stages) ------------- */
template<bool H16>
__global__ void k_bnapply(const float* __restrict__ g, const float* __restrict__ bb,
                          int sb) {
    int i4 = blockIdx.x * 256 + threadIdx.x;
    float4 v = ((const float4*)g_pre)[i4];
    int r = i4 >> 5;
    int n = r & 511;
    const float invC = 1.f / (float)(MBATCH * HID);
    float mean = g_bnsum[sb * NN + n] * invC;
    float var  = g_bnsq [sb * NN + n] * invC - mean * mean;
    var = fmaxf(var, 0.f);
    float sc = g[n] * rsqrtf(var + EPSV);
    float sh = bb[n] - mean * sc;
    float x0 = fmaxf(v.x * sc + sh, 0.f);
    float x1 = fmaxf(v.y * sc + sh, 0.f);
    float x2 = fmaxf(v.z * sc + sh, 0.f);
    float x3 = fmaxf(v.w * sc + sh, 0.f);
    __half2 p0 = __floats2half2_rn(x0, x1);
    __half2 p1 = __floats2half2_rn(x2, x3);
    uint2 u; u.x = *(unsigned*)&p0; u.y = *(unsigned*)&p1;
    ((uint2*)g_hh)[i4] = u;
    if (H16) {
        float w = g_inv[r];
        __half2 h0 = __floats2half2_rn(w * x0, w * x1);
        __half2 h1 = __floats2half2_rn(w * x2, w * x3);
        uint2 u2; u2.x = *(unsigned*)&h0; u2.y = *(unsigned*)&h1;
        ((uint2*)g_h16)[i4] = u2;
    }
}

/* ---------------- driver ------------------------------------------------ */
extern "C" void kernel_launch(void* const* d_in, const int* in_sizes, int n_in,
                              void* d_out, int out_size) {
    const float* x   = (const float*)d_in[0];
    const float* adj = (const float*)d_in[1];
    const float* ws[3] = {(const float*)d_in[2],  (const float*)d_in[8],  (const float*)d_in[14]};
    const float* bs[3] = {(const float*)d_in[3],  (const float*)d_in[9],  (const float*)d_in[15]};
    const float* we[3] = {(const float*)d_in[4],  (const float*)d_in[10], (const float*)d_in[16]};
    const float* be[3] = {(const float*)d_in[5],  (const float*)d_in[11], (const float*)d_in[17]};
    const float* bg[3] = {(const float*)d_in[6],  (const float*)d_in[12], (const float*)d_in[18]};
    const float* bb[3] = {(const float*)d_in[7],  (const float*)d_in[13], (const float*)d_in[19]};
    const float* w1  = (const float*)d_in[20];
    const float* b1  = (const float*)d_in[21];
    const float* bfg = (const float*)d_in[22];
    const float* bfb = (const float*)d_in[23];
    const float* w2  = (const float*)d_in[24];
    const float* b2  = (const float*)d_in[25];

    (void)in_sizes; (void)n_in; (void)out_size;

    k_csr<<<(MBATCH * ET * NN) / 8, 256>>>(adj);
    k_deg<<<(MBATCH * NN) / 256, 256>>>();
    k_prep2<<<NB_SSUM + NB_STAGE0 + NB_WPREP, 256>>>(
        x, ws[0], we[0], be[0], ws[1], we[1], be[1], ws[2], we[2], be[2], w1, w2);

    /* layer 0 */
    k_agg<IN0><<<ROWS, 128>>>(x, KP0);
    k_gemm<<<ROWS / 128, 256>>>(KP0, bs[0], 0, nullptr, WT0, 0);
    k_bnapply<true><<<ROWS * HID / 4 / 256, 256>>>(bg[0], bb[0], 0);

    /* layer 1 */
    k_agg<HID><<<ROWS, 128>>>((const float*)nullptr, KP12);
    k_gemm<<<ROWS / 128, 256>>>(KP12, bs[1], 0, nullptr, WT1, 1);
    k_bnapply<true><<<ROWS * HID / 4 / 256, 256>>>(bg[1], bb[1], 1);

    /* layer 2 */
    k_agg<HID><<<ROWS, 128>>>((const float*)nullptr, KP12);
    k_gemm<<<ROWS / 128, 256>>>(KP12, bs[2], 0, nullptr, WT2, 2);
    k_bnapply<true><<<ROWS * HID / 4 / 256, 256>>>(bg[2], bb[2], 2);

    /* final MLP */
    k_gemm<<<ROWS / 128, 256>>>(HID, b1, 1, nullptr, WT3, 3);
    k_bnapply<false><<<ROWS * HID / 4 / 256, 256>>>(bfg, bfb, 3);
    k_gemm<<<ROWS / 128, 256>>>(HID, b2, 1, (float*)d_out, WT4, -1);
}